// round 1
// baseline (speedup 1.0000x reference)
#include <cuda_runtime.h>
#include <math.h>

#define H    16
#define L    2048
#define DK   64
#define RB   32
#define ROWS 16

// Scratch: fused factor C (32 per row) and B factor (32 per row), per head*row.
__device__ float g_C[H * L * RB];
__device__ float g_B[H * L * RB];

// ---------------------------------------------------------------------------
// Kernel 1: projections.  C[m] = 32*(q.Wa[2m] + q.Wa[2m+1] + ba[2m]+ba[2m+1])
//           B[m] = q.Wb[m] + bb[m]
// One warp per (head,row); lane = factor index m.
// ---------------------------------------------------------------------------
__global__ void proj_kernel(const float* __restrict__ q,
                            const float* __restrict__ Wa, const float* __restrict__ ba,
                            const float* __restrict__ Wb, const float* __restrict__ bb) {
    __shared__ float qs[8][DK];
    int w = threadIdx.x >> 5, lane = threadIdx.x & 31;
    int row = blockIdx.x * 8 + w;                 // row in [0, H*L)
    const float* qr = q + (size_t)row * DK;
    qs[w][lane]      = qr[lane];
    qs[w][lane + 32] = qr[lane + 32];
    __syncwarp();
    int m = lane;
    const float* wa0 = Wa + (2 * m) * DK;
    const float* wa1 = Wa + (2 * m + 1) * DK;
    const float* wb  = Wb + m * DK;
    float ca = 0.f, cb = 0.f;
#pragma unroll
    for (int d = 0; d < DK; d++) {
        float qd = qs[w][d];
        ca += qd * (wa0[d] + wa1[d]);
        cb += qd * wb[d];
    }
    g_C[(size_t)row * RB + m] = 32.f * (ca + ba[2 * m] + ba[2 * m + 1]);
    g_B[(size_t)row * RB + m] = cb + bb[m];
}

// ---------------------------------------------------------------------------
// Kernel 2: fused attention. One CTA per (head, 16-row tile).
//  Phase 1: S[16][2048] = C_tile @ B_head^T   (K=32, fp32, S in smem)
//  Phase 2: row softmax in-place, write normalized P to global attn output
//  Phase 3: out = P @ v, streaming 128-column blocks (v tile + transposed P
//           staging in smem; LDS.128 broadcast of 4 rows' P per column)
// ---------------------------------------------------------------------------
__global__ __launch_bounds__(256, 1)
void attn_kernel(const float* __restrict__ v,
                 float* __restrict__ out,    // [H, L, DK]
                 float* __restrict__ attn) { // [H, L, L]
    extern __shared__ float sm[];
    float* S  = sm;                       // ROWS*L           = 32768 floats
    float* Cs = S + ROWS * L;             // ROWS*RB          = 512
    float* Pt = Cs + ROWS * RB;           // 128*20 (padded)  = 2560
    float* vs = Pt + 128 * 20;            // 128*64           = 8192

    int tid  = threadIdx.x;
    int lane = tid & 31, w = tid >> 5;
    int head = blockIdx.x >> 7;           // / 128 row-tiles
    int rt   = blockIdx.x & 127;
    int row0 = rt * ROWS;

    // Load C rows for this tile
    for (int i = tid; i < ROWS * RB; i += 256) {
        int r = i >> 5, m = i & 31;
        Cs[i] = g_C[(size_t)(head * L + row0 + r) * RB + m];
    }
    __syncthreads();

    // ---- Phase 1: S = C @ B^T --------------------------------------------
    for (int k = 0; k < L / 256; k++) {
        int j = tid + 256 * k;
        float b[RB];
        const float4* bp = (const float4*)(g_B + (size_t)(head * L + j) * RB);
#pragma unroll
        for (int i = 0; i < 8; i++) {
            float4 t = bp[i];
            b[4 * i] = t.x; b[4 * i + 1] = t.y; b[4 * i + 2] = t.z; b[4 * i + 3] = t.w;
        }
#pragma unroll 4
        for (int r = 0; r < ROWS; r++) {
            float acc = 0.f;
#pragma unroll
            for (int m = 0; m < RB; m++) acc += Cs[r * RB + m] * b[m];
            S[r * L + j] = acc;
        }
    }
    __syncthreads();

    // ---- Phase 2: softmax (warp w owns rows 2w, 2w+1) --------------------
    for (int rr = 0; rr < 2; rr++) {
        int r = 2 * w + rr;
        float* Sr = S + r * L;
        float mx = -1e30f;
#pragma unroll
        for (int k = 0; k < L / 32; k++) mx = fmaxf(mx, Sr[lane + 32 * k]);
#pragma unroll
        for (int o = 16; o > 0; o >>= 1) mx = fmaxf(mx, __shfl_xor_sync(0xffffffffu, mx, o));
        float sum = 0.f;
#pragma unroll
        for (int k = 0; k < L / 32; k++) {
            int idx = lane + 32 * k;
            float e = __expf(Sr[idx] - mx);
            Sr[idx] = e;
            sum += e;
        }
#pragma unroll
        for (int o = 16; o > 0; o >>= 1) sum += __shfl_xor_sync(0xffffffffu, sum, o);
        float inv = 1.f / sum;
        float* ar = attn + (size_t)(head * L + row0 + r) * L;
#pragma unroll
        for (int k = 0; k < L / 32; k++) {
            int idx = lane + 32 * k;
            float p = Sr[idx] * inv;
            Sr[idx] = p;            // keep normalized P for phase 3
            ar[idx] = p;            // write dense_attn output
        }
    }
    __syncthreads();

    // ---- Phase 3: out = P @ v --------------------------------------------
    // warp -> (row group of 4, d-half); lane -> d within half.
    int rg = w >> 1;                     // 0..3 -> rows rg*4 .. rg*4+3
    int d  = (w & 1) * 32 + lane;        // 0..63
    float acc0 = 0.f, acc1 = 0.f, acc2 = 0.f, acc3 = 0.f;

    for (int blk = 0; blk < 16; blk++) {
        int jb = blk * 128;
        // v tile: vs[j][d] for j in [jb, jb+128)
        const float4* vg = (const float4*)(v + (size_t)(head * L + jb) * DK);
        float4* vs4 = (float4*)vs;
#pragma unroll
        for (int i = 0; i < 8; i++) vs4[tid + 256 * i] = vg[tid + 256 * i];
        // transpose P chunk: Pt[j][r], padded row of 20 floats (16B-aligned groups)
#pragma unroll
        for (int i = 0; i < 8; i++) {
            int idx = tid + 256 * i;       // 0..2047
            int r = idx >> 7, j = idx & 127;
            Pt[j * 20 + r] = S[r * L + jb + j];
        }
        __syncthreads();
#pragma unroll 4
        for (int j = 0; j < 128; j++) {
            float4 p4 = *(const float4*)(Pt + j * 20 + rg * 4);   // broadcast
            float  vv = vs[j * DK + d];
            acc0 += p4.x * vv; acc1 += p4.y * vv;
            acc2 += p4.z * vv; acc3 += p4.w * vv;
        }
        __syncthreads();
    }

    float* o = out + (size_t)(head * L + row0 + rg * 4) * DK + d;
    o[0]      = acc0;
    o[DK]     = acc1;
    o[2 * DK] = acc2;
    o[3 * DK] = acc3;
}

// ---------------------------------------------------------------------------
extern "C" void kernel_launch(void* const* d_in, const int* in_sizes, int n_in,
                              void* d_out, int out_size) {
    const float* q  = (const float*)d_in[0];
    const float* v  = (const float*)d_in[1];
    const float* Wa = (const float*)d_in[2];
    const float* ba = (const float*)d_in[3];
    const float* Wb = (const float*)d_in[4];
    const float* bb = (const float*)d_in[5];

    float* out  = (float*)d_out;                     // [H, L, DK] first
    float* attn = out + (size_t)H * L * DK;          // then [H, L, L]

    const int smem = (ROWS * L + ROWS * RB + 128 * 20 + 128 * 64) * 4;  // 176128 B
    cudaFuncSetAttribute(attn_kernel, cudaFuncAttributeMaxDynamicSharedMemorySize, smem);

    proj_kernel<<<H * L / 8, 256>>>(q, Wa, ba, Wb, bb);
    attn_kernel<<<H * (L / ROWS), 256, smem>>>(v, out, attn);
}

// round 4
// speedup vs baseline: 1.2841x; 1.2841x over previous
#include <cuda_runtime.h>
#include <math.h>

#define H    16
#define L    2048
#define DK   64
#define RB   32
#define ROWS 16
#define SPAD 20          // padded row of S[j][.] in floats

// Scratch (device globals: no allocs allowed)
__device__ float g_C[H * L * RB];
__device__ float g_B[H * L * RB];
__device__ float g_Ut[DK * DK];   // combined weight, transposed: [k][o]
__device__ float g_us[DK];        // combined bias

// ---------------------------------------------------------------------------
// Kernel A: build combined weight U (o<32: 32*(Wa[2o]+Wa[2o+1]); else Wb[o-32])
// stored k-major for conflict-free smem reads later. One small CTA.
// ---------------------------------------------------------------------------
__global__ void buildU_kernel(const float* __restrict__ Wa, const float* __restrict__ ba,
                              const float* __restrict__ Wb, const float* __restrict__ bb) {
    for (int i = threadIdx.x; i < DK * DK; i += blockDim.x) {
        int k = i >> 6, o = i & 63;
        float u;
        if (o < 32) u = 32.f * (Wa[(2 * o) * DK + k] + Wa[(2 * o + 1) * DK + k]);
        else        u = Wb[(o - 32) * DK + k];
        g_Ut[k * DK + o] = u;
    }
    if (threadIdx.x < DK) {
        int o = threadIdx.x;
        g_us[o] = (o < 32) ? 32.f * (ba[2 * o] + ba[2 * o + 1]) : bb[o - 32];
    }
}

// ---------------------------------------------------------------------------
// Kernel B: projections as a register-blocked mini-GEMM.
// CTA = 64 q-rows, 256 threads, 4x4 register tile per thread.
// Outputs: g_C[row][0:32] (fused a-factor), g_B[row][0:32] (b-factor).
// ---------------------------------------------------------------------------
__global__ __launch_bounds__(256)
void proj_kernel(const float* __restrict__ q) {
    __shared__ float Ut[DK * DK];   // [k][o]
    __shared__ float us[DK];
    __shared__ float qs[64 * DK];   // [r][k]
    int tid = threadIdx.x;
    int row0 = blockIdx.x * 64;

    {
        float4* d4 = (float4*)Ut;  const float4* s4 = (const float4*)g_Ut;
        for (int i = tid; i < DK * DK / 4; i += 256) d4[i] = s4[i];
        if (tid < DK) us[tid] = g_us[tid];
        float4* q4 = (float4*)qs;  const float4* g4 = (const float4*)(q + (size_t)row0 * DK);
        for (int i = tid; i < 64 * DK / 4; i += 256) q4[i] = g4[i];
    }
    __syncthreads();

    int tr = tid >> 4, tc = tid & 15;         // rows 4tr.., outs 4tc..
    float acc[4][4] = {};
#pragma unroll 8
    for (int k = 0; k < DK; k++) {
        float4 u = *(const float4*)(Ut + k * DK + 4 * tc);
        float qv[4];
#pragma unroll
        for (int ri = 0; ri < 4; ri++) qv[ri] = qs[(4 * tr + ri) * DK + k];
#pragma unroll
        for (int ri = 0; ri < 4; ri++) {
            acc[ri][0] += qv[ri] * u.x;  acc[ri][1] += qv[ri] * u.y;
            acc[ri][2] += qv[ri] * u.z;  acc[ri][3] += qv[ri] * u.w;
        }
    }
    float4 ub = *(const float4*)(us + 4 * tc);
#pragma unroll
    for (int ri = 0; ri < 4; ri++) {
        int row = row0 + 4 * tr + ri;
        float4 o = make_float4(acc[ri][0] + ub.x, acc[ri][1] + ub.y,
                               acc[ri][2] + ub.z, acc[ri][3] + ub.w);
        if (tc < 8) *(float4*)(g_C + (size_t)row * RB + 4 * tc)        = o;
        else        *(float4*)(g_B + (size_t)row * RB + (4 * tc - 32)) = o;
    }
}

// ---------------------------------------------------------------------------
// Kernel C: fused attention. One CTA per (head, 16-row tile), 512 threads.
//  Phase 1: S[j][r] (transposed, pad 20) = C_tile @ B^T via swizzled B chunks,
//           B row in registers, C via broadcast LDS.128.
//  Phase 2: softmax per row (warp-per-row), write dense_attn.
//  Phase 3: out = P @ v; thread owns (d, j-group), 16 rows accumulated in regs,
//           P read as 4 broadcast LDS.128; cross-group smem reduction.
// ---------------------------------------------------------------------------
__global__ __launch_bounds__(512, 1)
void attn_kernel(const float* __restrict__ v,
                 float* __restrict__ out,    // [H, L, DK]
                 float* __restrict__ attn) { // [H, L, L]
    extern __shared__ float sm[];
    float* S   = sm;                  // L * SPAD        = 40960 floats
    float* Cs  = S + L * SPAD;        // ROWS * RB       = 512
    float* buf = Cs + ROWS * RB;      // 8192 floats (B chunk / v chunk / reduce)

    int tid  = threadIdx.x;
    int lane = tid & 31, w = tid >> 5;
    int head = blockIdx.x >> 7;
    int rt   = blockIdx.x & 127;
    int row0 = rt * ROWS;

    // C tile for these 16 rows
    {
        const float4* c4 = (const float4*)(g_C + (size_t)(head * L + row0) * RB);
        float4* d4 = (float4*)Cs;
        for (int i = tid; i < ROWS * RB / 4; i += 512) d4[i] = c4[i];
    }

    // ---- Phase 1: S[j][r] = sum_m C[r][m] * B[j][m] --------------------------
    const float* gB = g_B + (size_t)head * L * RB;
    int jj = tid & 255, rh = tid >> 8;     // column within chunk, row-half
    for (int c = 0; c < 8; c++) {
        __syncthreads();                   // buf reuse guard (also covers Cs load)
        int j0 = c * 256;
        // stage swizzled B chunk: 256 j x 32 floats
#pragma unroll
        for (int t = 0; t < 4; t++) {
            int idx4 = tid + 512 * t;              // float4 index, 0..2047
            int j = idx4 >> 3, i = idx4 & 7;
            float4 bv = *(const float4*)(gB + (size_t)(j0 + j) * RB + 4 * i);
            *(float4*)(buf + j * RB + 4 * (i ^ (j & 7))) = bv;
        }
        __syncthreads();
        float4 b4[8];
#pragma unroll
        for (int i = 0; i < 8; i++)
            b4[i] = *(const float4*)(buf + jj * RB + 4 * (i ^ (jj & 7)));
        float acc[8];
#pragma unroll
        for (int r = 0; r < 8; r++) {
            int row = rh * 8 + r;
            float a = 0.f;
#pragma unroll
            for (int i = 0; i < 8; i++) {
                float4 cv = *(const float4*)(Cs + row * RB + 4 * i);  // broadcast
                a += cv.x * b4[i].x + cv.y * b4[i].y + cv.z * b4[i].z + cv.w * b4[i].w;
            }
            acc[r] = a;
        }
        float* Sr = S + (size_t)(j0 + jj) * SPAD + rh * 8;
        *(float4*)(Sr)     = make_float4(acc[0], acc[1], acc[2], acc[3]);
        *(float4*)(Sr + 4) = make_float4(acc[4], acc[5], acc[6], acc[7]);
    }
    __syncthreads();

    // ---- Phase 2: softmax, warp w owns row w --------------------------------
    {
        int r = w;
        float mx = -1e30f;
#pragma unroll
        for (int k = 0; k < 64; k++) mx = fmaxf(mx, S[(lane + 32 * k) * SPAD + r]);
#pragma unroll
        for (int o = 16; o > 0; o >>= 1) mx = fmaxf(mx, __shfl_xor_sync(0xffffffffu, mx, o));
        float sum = 0.f;
#pragma unroll
        for (int k = 0; k < 64; k++) {
            int idx = (lane + 32 * k) * SPAD + r;
            float e = __expf(S[idx] - mx);
            S[idx] = e;
            sum += e;
        }
#pragma unroll
        for (int o = 16; o > 0; o >>= 1) sum += __shfl_xor_sync(0xffffffffu, sum, o);
        float inv = 1.f / sum;
        float* ar = attn + (size_t)(head * L + row0 + r) * L;
#pragma unroll
        for (int k = 0; k < 64; k++) {
            int j = lane + 32 * k;
            float p = S[j * SPAD + r] * inv;
            S[j * SPAD + r] = p;      // keep normalized P
            ar[j] = p;                // dense_attn output (coalesced)
        }
    }

    // ---- Phase 3: out = P @ v ----------------------------------------------
    int d = tid & 63, jg = tid >> 6;          // d-lane, j-group (0..7)
    float acc[16];
#pragma unroll
    for (int r = 0; r < 16; r++) acc[r] = 0.f;
    const float* gv = v + (size_t)head * L * DK;

    for (int c = 0; c < 16; c++) {
        int j0 = c * 128;
        __syncthreads();                       // buf reuse guard
#pragma unroll
        for (int t = 0; t < 4; t++) {
            int idx4 = tid + 512 * t;          // 0..2047 float4s = 128 j x 16
            int j = idx4 >> 4, dd = idx4 & 15;
            *(float4*)(buf + j * DK + 4 * dd) =
                *(const float4*)(gv + (size_t)(j0 + j) * DK + 4 * dd);
        }
        __syncthreads();
#pragma unroll
        for (int t = 0; t < 16; t++) {
            int j = jg * 16 + t;
            const float* Pr = S + (size_t)(j0 + j) * SPAD;
            float4 p0 = *(const float4*)(Pr);        // broadcast
            float4 p1 = *(const float4*)(Pr + 4);
            float4 p2 = *(const float4*)(Pr + 8);
            float4 p3 = *(const float4*)(Pr + 12);
            float vv = buf[j * DK + d];
            acc[0]  += p0.x * vv;  acc[1]  += p0.y * vv;
            acc[2]  += p0.z * vv;  acc[3]  += p0.w * vv;
            acc[4]  += p1.x * vv;  acc[5]  += p1.y * vv;
            acc[6]  += p1.z * vv;  acc[7]  += p1.w * vv;
            acc[8]  += p2.x * vv;  acc[9]  += p2.y * vv;
            acc[10] += p2.z * vv;  acc[11] += p2.w * vv;
            acc[12] += p3.x * vv;  acc[13] += p3.y * vv;
            acc[14] += p3.z * vv;  acc[15] += p3.w * vv;
        }
    }
    __syncthreads();
    // cross-jg reduction via buf laid out [r][d][jg] (16*64*8 = 8192 floats)
#pragma unroll
    for (int r = 0; r < 16; r++) buf[(r * DK + d) * 8 + jg] = acc[r];
    __syncthreads();
#pragma unroll
    for (int s = 0; s < 2; s++) {
        int oidx = tid + 512 * s;              // 0..1023 = 16 rows x 64 d
        int r = oidx >> 6, dd = oidx & 63;
        const float* p = buf + (r * DK + dd) * 8;
        float4 a = *(const float4*)p, b = *(const float4*)(p + 4);
        float sum = a.x + a.y + a.z + a.w + b.x + b.y + b.z + b.w;
        out[(size_t)(head * L + row0 + r) * DK + dd] = sum;
    }
}

// ---------------------------------------------------------------------------
extern "C" void kernel_launch(void* const* d_in, const int* in_sizes, int n_in,
                              void* d_out, int out_size) {
    const float* q  = (const float*)d_in[0];
    const float* v  = (const float*)d_in[1];
    const float* Wa = (const float*)d_in[2];
    const float* ba = (const float*)d_in[3];
    const float* Wb = (const float*)d_in[4];
    const float* bb = (const float*)d_in[5];

    float* out  = (float*)d_out;                 // [H, L, DK]
    float* attn = out + (size_t)H * L * DK;      // [H, L, L]

    const int smem = (L * SPAD + ROWS * RB + 8192) * 4;   // 198656 B
    cudaFuncSetAttribute(attn_kernel, cudaFuncAttributeMaxDynamicSharedMemorySize, smem);

    buildU_kernel<<<1, 256>>>(Wa, ba, Wb, bb);
    proj_kernel<<<H * L / 64, 256>>>(q);
    attn_kernel<<<H * (L / ROWS), 512, smem>>>(v, out, attn);
}

// round 5
// speedup vs baseline: 2.2894x; 1.7829x over previous
#include <cuda_runtime.h>
#include <math.h>

#define H    16
#define L    2048
#define DK   64
#define RB   32
#define ROWS 16
#define SPAD 20          // padded row of S[j][.] in floats (16 data + 4 pad)

// Scratch (device globals: no allocs allowed)
__device__ float g_C[H * L * RB];
__device__ float g_B[H * L * RB];

// ---- f32x2 packed helpers --------------------------------------------------
typedef unsigned long long u64;

__device__ __forceinline__ u64 pk(float lo, float hi) {
    u64 r; asm("mov.b64 %0, {%1, %2};" : "=l"(r) : "f"(lo), "f"(hi)); return r;
}
__device__ __forceinline__ void fma2(u64 &acc, u64 a, u64 b) {
    asm("fma.rn.f32x2 %0, %1, %2, %0;" : "+l"(acc) : "l"(a), "l"(b));
}
__device__ __forceinline__ float2 upk(u64 v) {
    float2 r; asm("mov.b64 {%0, %1}, %2;" : "=f"(r.x), "=f"(r.y) : "l"(v)); return r;
}

// ---------------------------------------------------------------------------
// Kernel 1: projections (U built in-CTA; Wa/Wb are tiny and L1-hot).
// CTA = 64 q-rows, 256 threads, 4x4 register tile per thread.
// C[m] = 32*(q.(Wa[2m]+Wa[2m+1]) + ba[2m]+ba[2m+1]);  B[m] = q.Wb[m] + bb[m]
// ---------------------------------------------------------------------------
__global__ __launch_bounds__(256)
void proj_kernel(const float* __restrict__ q,
                 const float* __restrict__ Wa, const float* __restrict__ ba,
                 const float* __restrict__ Wb, const float* __restrict__ bb) {
    __shared__ float Ut[DK * DK];   // [k][o]
    __shared__ float us[DK];
    __shared__ float qs[64 * DK];   // [r][k]
    int tid = threadIdx.x;
    int row0 = blockIdx.x * 64;

    // Build combined weight (coalesced LDG over k; Wa/Wb stay L1-resident)
    for (int i = tid; i < DK * DK; i += 256) {
        int o = i >> 6, k = i & 63;
        float u;
        if (o < 32) u = 32.f * (Wa[(2 * o) * DK + k] + Wa[(2 * o + 1) * DK + k]);
        else        u = Wb[(o - 32) * DK + k];
        Ut[k * DK + o] = u;
    }
    if (tid < DK)
        us[tid] = (tid < 32) ? 32.f * (ba[2 * tid] + ba[2 * tid + 1]) : bb[tid - 32];
    {
        float4* q4 = (float4*)qs;  const float4* g4 = (const float4*)(q + (size_t)row0 * DK);
        for (int i = tid; i < 64 * DK / 4; i += 256) q4[i] = g4[i];
    }
    __syncthreads();

    int tr = tid >> 4, tc = tid & 15;         // rows 4tr.., outs 4tc..
    float acc[4][4] = {};
#pragma unroll 8
    for (int k = 0; k < DK; k++) {
        float4 u = *(const float4*)(Ut + k * DK + 4 * tc);
        float qv[4];
#pragma unroll
        for (int ri = 0; ri < 4; ri++) qv[ri] = qs[(4 * tr + ri) * DK + k];
#pragma unroll
        for (int ri = 0; ri < 4; ri++) {
            acc[ri][0] += qv[ri] * u.x;  acc[ri][1] += qv[ri] * u.y;
            acc[ri][2] += qv[ri] * u.z;  acc[ri][3] += qv[ri] * u.w;
        }
    }
    float4 ub = *(const float4*)(us + 4 * tc);
#pragma unroll
    for (int ri = 0; ri < 4; ri++) {
        int row = row0 + 4 * tr + ri;
        float4 o = make_float4(acc[ri][0] + ub.x, acc[ri][1] + ub.y,
                               acc[ri][2] + ub.z, acc[ri][3] + ub.w);
        if (tc < 8) *(float4*)(g_C + (size_t)row * RB + 4 * tc)        = o;
        else        *(float4*)(g_B + (size_t)row * RB + (4 * tc - 32)) = o;
    }
}

// ---------------------------------------------------------------------------
// Kernel 2: fused attention. One CTA per (head, 16-row tile), 512 threads.
// S layout: S[j][16] rows in 4 float4-groups, group g stored at slot g^((j>>3)&1)
//   (breaks the stride-20 lane-quartet bank collision).
//  Phase 1: S = C @ B^T, f32x2 packed over m-pairs.
//  Phase 2: 3-pass softmax (max / exp+sum / scale+STG); inv kept in smem.
//  Phase 3: E @ v with f32x2 over row-pairs; epilogue scales by inv[r].
// ---------------------------------------------------------------------------
__global__ __launch_bounds__(512, 1)
void attn_kernel(const float* __restrict__ v,
                 float* __restrict__ out,    // [H, L, DK]
                 float* __restrict__ attn) { // [H, L, L]
    extern __shared__ float sm[];
    float* S   = sm;                  // L * SPAD  = 40960 floats
    float* Cs  = S + L * SPAD;        // ROWS * RB = 512 (later: inv[16])
    float* buf = Cs + ROWS * RB;      // 8192 floats (B chunk / v chunk / reduce)

    int tid  = threadIdx.x;
    int lane = tid & 31, w = tid >> 5;
    int head = blockIdx.x >> 7;
    int rt   = blockIdx.x & 127;
    int row0 = rt * ROWS;

    // C tile for these 16 rows
    {
        const float4* c4 = (const float4*)(g_C + (size_t)(head * L + row0) * RB);
        float4* d4 = (float4*)Cs;
        for (int i = tid; i < ROWS * RB / 4; i += 512) d4[i] = c4[i];
    }

    // ---- Phase 1: S[j][r] = sum_m C[r][m] * B[j][m] (f32x2 over m-pairs) ----
    const float* gB = g_B + (size_t)head * L * RB;
    int jj = tid & 255, rh = tid >> 8;     // column within chunk, row-half
    for (int c = 0; c < 8; c++) {
        __syncthreads();                   // buf reuse guard (covers Cs fill too)
        int j0 = c * 256;
        // stage swizzled B chunk: 256 j x 32 floats
#pragma unroll
        for (int t = 0; t < 4; t++) {
            int idx4 = tid + 512 * t;              // float4 index, 0..2047
            int j = idx4 >> 3, i = idx4 & 7;
            float4 bv = *(const float4*)(gB + (size_t)(j0 + j) * RB + 4 * i);
            *(float4*)(buf + j * RB + 4 * (i ^ (j & 7))) = bv;
        }
        __syncthreads();
        u64 b2[16];
#pragma unroll
        for (int i = 0; i < 8; i++) {
            ulonglong2 t2 = *(const ulonglong2*)(buf + jj * RB + 4 * (i ^ (jj & 7)));
            b2[2 * i] = t2.x;  b2[2 * i + 1] = t2.y;
        }
        float s[8];
#pragma unroll
        for (int r = 0; r < 8; r++) {
            int row = rh * 8 + r;
            u64 a2 = 0ull;
#pragma unroll
            for (int i = 0; i < 8; i++) {
                ulonglong2 c2 = *(const ulonglong2*)(Cs + row * RB + 4 * i); // bcast
                fma2(a2, c2.x, b2[2 * i]);
                fma2(a2, c2.y, b2[2 * i + 1]);
            }
            float2 t = upk(a2);
            s[r] = t.x + t.y;
        }
        int key = (jj >> 3) & 1;
        float* Sr = S + (size_t)(j0 + jj) * SPAD;
        *(float4*)(Sr + 4 * ((2 * rh)     ^ key)) = make_float4(s[0], s[1], s[2], s[3]);
        *(float4*)(Sr + 4 * ((2 * rh + 1) ^ key)) = make_float4(s[4], s[5], s[6], s[7]);
    }
    __syncthreads();

    // ---- Phase 2: softmax, warp w owns row w (3 passes) ---------------------
    {
        int r = w, g = r >> 2, e = r & 3;
        int off = 4 * (g ^ ((lane >> 3) & 1)) + e;   // per-lane constant slot
        float mx = -1e30f;
#pragma unroll
        for (int k = 0; k < 64; k++) mx = fmaxf(mx, S[(lane + 32 * k) * SPAD + off]);
#pragma unroll
        for (int o = 16; o > 0; o >>= 1) mx = fmaxf(mx, __shfl_xor_sync(0xffffffffu, mx, o));
        float sum = 0.f;
#pragma unroll
        for (int k = 0; k < 64; k++) {
            int idx = (lane + 32 * k) * SPAD + off;
            float ee = __expf(S[idx] - mx);
            S[idx] = ee;                  // keep unnormalized E
            sum += ee;
        }
#pragma unroll
        for (int o = 16; o > 0; o >>= 1) sum += __shfl_xor_sync(0xffffffffu, sum, o);
        float inv = 1.f / sum;
        if (lane == 0) Cs[r] = inv;       // Cs no longer needed as C
        float* ar = attn + (size_t)(head * L + row0 + r) * L;
#pragma unroll
        for (int k = 0; k < 64; k++) {
            int j = lane + 32 * k;
            ar[j] = S[j * SPAD + off] * inv;   // dense_attn (coalesced STG)
        }
    }

    // ---- Phase 3: out = E @ v (scale by inv at the end) ---------------------
    int d0 = tid & 31, jg = tid >> 5;     // 2 d per thread, 8-j group
    int key3 = jg & 1;                    // = (j>>3)&1 for all j in this group
    u64 acc2[16];                         // [rp][dh], rp=row-pair 0..7, dh=0..1
#pragma unroll
    for (int i = 0; i < 16; i++) acc2[i] = 0ull;
    const float* gv = v + (size_t)head * L * DK;

    for (int c = 0; c < 16; c++) {
        int j0 = c * 128;
        __syncthreads();                       // buf reuse guard
#pragma unroll
        for (int t = 0; t < 4; t++) {
            int idx4 = tid + 512 * t;          // 128 j x 16 float4
            int j = idx4 >> 4, dd = idx4 & 15;
            *(float4*)(buf + j * DK + 4 * dd) =
                *(const float4*)(gv + (size_t)(j0 + j) * DK + 4 * dd);
        }
        __syncthreads();
#pragma unroll
        for (int t = 0; t < 8; t++) {
            int j = jg * 8 + t;
            const float* Sj = S + (size_t)(j0 + j) * SPAD;
            ulonglong2 p0 = *(const ulonglong2*)(Sj + 4 * (0 ^ key3));  // rows 0-3
            ulonglong2 p1 = *(const ulonglong2*)(Sj + 4 * (1 ^ key3));  // rows 4-7
            ulonglong2 p2 = *(const ulonglong2*)(Sj + 4 * (2 ^ key3));  // rows 8-11
            ulonglong2 p3 = *(const ulonglong2*)(Sj + 4 * (3 ^ key3));  // rows 12-15
            float v0 = buf[j * DK + d0];
            float v1 = buf[j * DK + d0 + 32];
            u64 vv0 = pk(v0, v0), vv1 = pk(v1, v1);
            fma2(acc2[0],  p0.x, vv0);  fma2(acc2[1],  p0.x, vv1);
            fma2(acc2[2],  p0.y, vv0);  fma2(acc2[3],  p0.y, vv1);
            fma2(acc2[4],  p1.x, vv0);  fma2(acc2[5],  p1.x, vv1);
            fma2(acc2[6],  p1.y, vv0);  fma2(acc2[7],  p1.y, vv1);
            fma2(acc2[8],  p2.x, vv0);  fma2(acc2[9],  p2.x, vv1);
            fma2(acc2[10], p2.y, vv0);  fma2(acc2[11], p2.y, vv1);
            fma2(acc2[12], p3.x, vv0);  fma2(acc2[13], p3.x, vv1);
            fma2(acc2[14], p3.y, vv0);  fma2(acc2[15], p3.y, vv1);
        }
    }

    // unpack: accf[k], k = rp*4 + dh*2 + half  (half: 0 = row 2rp, 1 = row 2rp+1)
    float accf[32];
#pragma unroll
    for (int rp = 0; rp < 8; rp++)
#pragma unroll
        for (int dh = 0; dh < 2; dh++) {
            float2 t = upk(acc2[rp * 2 + dh]);
            accf[rp * 4 + dh * 2 + 0] = t.x;
            accf[rp * 4 + dh * 2 + 1] = t.y;
        }

    // two-stage reduction across 16 jg groups (buf layout: k*256 + jg*32 + d0)
    __syncthreads();
    if (jg >= 8) {
        int base = (jg - 8) * 32 + d0;
#pragma unroll
        for (int k = 0; k < 32; k++) buf[k * 256 + base] = accf[k];
    }
    __syncthreads();
    if (jg < 8) {
        int base = jg * 32 + d0;
#pragma unroll
        for (int k = 0; k < 32; k++) accf[k] += buf[k * 256 + base];
    }
    __syncthreads();
    if (jg < 8) {
        int base = jg * 32 + d0;
#pragma unroll
        for (int k = 0; k < 32; k++) buf[k * 256 + base] = accf[k];
    }
    __syncthreads();
#pragma unroll
    for (int s = 0; s < 2; s++) {
        int oidx = tid + 512 * s;              // 1024 outputs = 16 r x 64 d
        int r = oidx >> 6, d = oidx & 63;
        int rp = r >> 1, half = r & 1, dh = d >> 5, dd0 = d & 31;
        int k = rp * 4 + dh * 2 + half;
        const float* p = buf + k * 256 + dd0;
        float sum = 0.f;
#pragma unroll
        for (int jg2 = 0; jg2 < 8; jg2++) sum += p[jg2 * 32];
        out[(size_t)(head * L + row0 + r) * DK + d] = sum * Cs[r];
    }
}

// ---------------------------------------------------------------------------
extern "C" void kernel_launch(void* const* d_in, const int* in_sizes, int n_in,
                              void* d_out, int out_size) {
    const float* q  = (const float*)d_in[0];
    const float* v  = (const float*)d_in[1];
    const float* Wa = (const float*)d_in[2];
    const float* ba = (const float*)d_in[3];
    const float* Wb = (const float*)d_in[4];
    const float* bb = (const float*)d_in[5];

    float* out  = (float*)d_out;                 // [H, L, DK]
    float* attn = out + (size_t)H * L * DK;      // [H, L, L]

    const int smem = (L * SPAD + ROWS * RB + 8192) * 4;   // 198656 B
    cudaFuncSetAttribute(attn_kernel, cudaFuncAttributeMaxDynamicSharedMemorySize, smem);

    proj_kernel<<<H * L / 64, 256>>>(q, Wa, ba, Wb, bb);
    attn_kernel<<<H * (L / ROWS), 512, smem>>>(v, out, attn);
}

// round 6
// speedup vs baseline: 2.3054x; 1.0070x over previous
#include <cuda_runtime.h>
#include <math.h>

#define H    16
#define L    2048
#define DK   64
#define RB   32
#define ROWS 16
#define SPAD 20          // padded row of S[j][.] in floats (16 data + 4 pad)

// Scratch (device globals: no allocs allowed)
__device__ float g_C[H * L * RB];
__device__ float g_B[H * L * RB];

// ---- f32x2 packed helpers --------------------------------------------------
typedef unsigned long long u64;

__device__ __forceinline__ u64 pk(float lo, float hi) {
    u64 r; asm("mov.b64 %0, {%1, %2};" : "=l"(r) : "f"(lo), "f"(hi)); return r;
}
__device__ __forceinline__ void fma2(u64 &acc, u64 a, u64 b) {
    asm("fma.rn.f32x2 %0, %1, %2, %0;" : "+l"(acc) : "l"(a), "l"(b));
}
__device__ __forceinline__ float2 upk(u64 v) {
    float2 r; asm("mov.b64 {%0, %1}, %2;" : "=f"(r.x), "=f"(r.y) : "l"(v)); return r;
}

// ---------------------------------------------------------------------------
// Kernel 1: projections (U built in-CTA; Wa/Wb are tiny and L1-hot).
// CTA = 64 q-rows, 256 threads, 4x4 register tile per thread.
// C[m] = 32*(q.(Wa[2m]+Wa[2m+1]) + ba[2m]+ba[2m+1]);  B[m] = q.Wb[m] + bb[m]
// ---------------------------------------------------------------------------
__global__ __launch_bounds__(256)
void proj_kernel(const float* __restrict__ q,
                 const float* __restrict__ Wa, const float* __restrict__ ba,
                 const float* __restrict__ Wb, const float* __restrict__ bb) {
    __shared__ float Ut[DK * DK];   // [k][o]
    __shared__ float us[DK];
    __shared__ float qs[64 * DK];   // [r][k]
    int tid = threadIdx.x;
    int row0 = blockIdx.x * 64;

    // Build combined weight (coalesced LDG over k; Wa/Wb stay L1-resident)
    for (int i = tid; i < DK * DK; i += 256) {
        int o = i >> 6, k = i & 63;
        float u;
        if (o < 32) u = 32.f * (Wa[(2 * o) * DK + k] + Wa[(2 * o + 1) * DK + k]);
        else        u = Wb[(o - 32) * DK + k];
        Ut[k * DK + o] = u;
    }
    if (tid < DK)
        us[tid] = (tid < 32) ? 32.f * (ba[2 * tid] + ba[2 * tid + 1]) : bb[tid - 32];
    {
        float4* q4 = (float4*)qs;  const float4* g4 = (const float4*)(q + (size_t)row0 * DK);
        for (int i = tid; i < 64 * DK / 4; i += 256) q4[i] = g4[i];
    }
    __syncthreads();

    int tr = tid >> 4, tc = tid & 15;         // rows 4tr.., outs 4tc..
    float acc[4][4] = {};
#pragma unroll 8
    for (int k = 0; k < DK; k++) {
        float4 u = *(const float4*)(Ut + k * DK + 4 * tc);
        float qv[4];
#pragma unroll
        for (int ri = 0; ri < 4; ri++) qv[ri] = qs[(4 * tr + ri) * DK + k];
#pragma unroll
        for (int ri = 0; ri < 4; ri++) {
            acc[ri][0] += qv[ri] * u.x;  acc[ri][1] += qv[ri] * u.y;
            acc[ri][2] += qv[ri] * u.z;  acc[ri][3] += qv[ri] * u.w;
        }
    }
    float4 ub = *(const float4*)(us + 4 * tc);
#pragma unroll
    for (int ri = 0; ri < 4; ri++) {
        int row = row0 + 4 * tr + ri;
        float4 o = make_float4(acc[ri][0] + ub.x, acc[ri][1] + ub.y,
                               acc[ri][2] + ub.z, acc[ri][3] + ub.w);
        if (tc < 8) *(float4*)(g_C + (size_t)row * RB + 4 * tc)        = o;
        else        *(float4*)(g_B + (size_t)row * RB + (4 * tc - 32)) = o;
    }
}

// ---------------------------------------------------------------------------
// Kernel 2: fused attention. One CTA per (head, 16-row tile), 512 threads.
// S layout: S[j][16] rows in 4 float4-groups, group g stored at slot g^((j>>3)&1)
//   (breaks the stride-20 lane-quartet bank collision).
//  Phase 1: S = C @ B^T, f32x2 packed over m-pairs.
//  Phase 2: 3-pass softmax (max / exp+sum / scale+STG); inv kept in smem.
//  Phase 3: E @ v with f32x2 over row-pairs; epilogue scales by inv[r].
// ---------------------------------------------------------------------------
__global__ __launch_bounds__(512, 1)
void attn_kernel(const float* __restrict__ v,
                 float* __restrict__ out,    // [H, L, DK]
                 float* __restrict__ attn) { // [H, L, L]
    extern __shared__ float sm[];
    float* S   = sm;                  // L * SPAD  = 40960 floats
    float* Cs  = S + L * SPAD;        // ROWS * RB = 512 (later: inv[16])
    float* buf = Cs + ROWS * RB;      // 8192 floats (B chunk / v chunk / reduce)

    int tid  = threadIdx.x;
    int lane = tid & 31, w = tid >> 5;
    int head = blockIdx.x >> 7;
    int rt   = blockIdx.x & 127;
    int row0 = rt * ROWS;

    // C tile for these 16 rows
    {
        const float4* c4 = (const float4*)(g_C + (size_t)(head * L + row0) * RB);
        float4* d4 = (float4*)Cs;
        for (int i = tid; i < ROWS * RB / 4; i += 512) d4[i] = c4[i];
    }

    // ---- Phase 1: S[j][r] = sum_m C[r][m] * B[j][m] (f32x2 over m-pairs) ----
    const float* gB = g_B + (size_t)head * L * RB;
    int jj = tid & 255, rh = tid >> 8;     // column within chunk, row-half
    for (int c = 0; c < 8; c++) {
        __syncthreads();                   // buf reuse guard (covers Cs fill too)
        int j0 = c * 256;
        // stage swizzled B chunk: 256 j x 32 floats
#pragma unroll
        for (int t = 0; t < 4; t++) {
            int idx4 = tid + 512 * t;              // float4 index, 0..2047
            int j = idx4 >> 3, i = idx4 & 7;
            float4 bv = *(const float4*)(gB + (size_t)(j0 + j) * RB + 4 * i);
            *(float4*)(buf + j * RB + 4 * (i ^ (j & 7))) = bv;
        }
        __syncthreads();
        u64 b2[16];
#pragma unroll
        for (int i = 0; i < 8; i++) {
            ulonglong2 t2 = *(const ulonglong2*)(buf + jj * RB + 4 * (i ^ (jj & 7)));
            b2[2 * i] = t2.x;  b2[2 * i + 1] = t2.y;
        }
        float s[8];
#pragma unroll
        for (int r = 0; r < 8; r++) {
            int row = rh * 8 + r;
            u64 a2 = 0ull;
#pragma unroll
            for (int i = 0; i < 8; i++) {
                ulonglong2 c2 = *(const ulonglong2*)(Cs + row * RB + 4 * i); // bcast
                fma2(a2, c2.x, b2[2 * i]);
                fma2(a2, c2.y, b2[2 * i + 1]);
            }
            float2 t = upk(a2);
            s[r] = t.x + t.y;
        }
        int key = (jj >> 3) & 1;
        float* Sr = S + (size_t)(j0 + jj) * SPAD;
        *(float4*)(Sr + 4 * ((2 * rh)     ^ key)) = make_float4(s[0], s[1], s[2], s[3]);
        *(float4*)(Sr + 4 * ((2 * rh + 1) ^ key)) = make_float4(s[4], s[5], s[6], s[7]);
    }
    __syncthreads();

    // ---- Phase 2: softmax, warp w owns row w (3 passes) ---------------------
    {
        int r = w, g = r >> 2, e = r & 3;
        int off = 4 * (g ^ ((lane >> 3) & 1)) + e;   // per-lane constant slot
        float mx = -1e30f;
#pragma unroll
        for (int k = 0; k < 64; k++) mx = fmaxf(mx, S[(lane + 32 * k) * SPAD + off]);
#pragma unroll
        for (int o = 16; o > 0; o >>= 1) mx = fmaxf(mx, __shfl_xor_sync(0xffffffffu, mx, o));
        float sum = 0.f;
#pragma unroll
        for (int k = 0; k < 64; k++) {
            int idx = (lane + 32 * k) * SPAD + off;
            float ee = __expf(S[idx] - mx);
            S[idx] = ee;                  // keep unnormalized E
            sum += ee;
        }
#pragma unroll
        for (int o = 16; o > 0; o >>= 1) sum += __shfl_xor_sync(0xffffffffu, sum, o);
        float inv = 1.f / sum;
        if (lane == 0) Cs[r] = inv;       // Cs no longer needed as C
        float* ar = attn + (size_t)(head * L + row0 + r) * L;
#pragma unroll
        for (int k = 0; k < 64; k++) {
            int j = lane + 32 * k;
            ar[j] = S[j * SPAD + off] * inv;   // dense_attn (coalesced STG)
        }
    }

    // ---- Phase 3: out = E @ v (scale by inv at the end) ---------------------
    int d0 = tid & 31, jg = tid >> 5;     // 2 d per thread, 8-j group
    int key3 = jg & 1;                    // = (j>>3)&1 for all j in this group
    u64 acc2[16];                         // [rp][dh], rp=row-pair 0..7, dh=0..1
#pragma unroll
    for (int i = 0; i < 16; i++) acc2[i] = 0ull;
    const float* gv = v + (size_t)head * L * DK;

    for (int c = 0; c < 16; c++) {
        int j0 = c * 128;
        __syncthreads();                       // buf reuse guard
#pragma unroll
        for (int t = 0; t < 4; t++) {
            int idx4 = tid + 512 * t;          // 128 j x 16 float4
            int j = idx4 >> 4, dd = idx4 & 15;
            *(float4*)(buf + j * DK + 4 * dd) =
                *(const float4*)(gv + (size_t)(j0 + j) * DK + 4 * dd);
        }
        __syncthreads();
#pragma unroll
        for (int t = 0; t < 8; t++) {
            int j = jg * 8 + t;
            const float* Sj = S + (size_t)(j0 + j) * SPAD;
            ulonglong2 p0 = *(const ulonglong2*)(Sj + 4 * (0 ^ key3));  // rows 0-3
            ulonglong2 p1 = *(const ulonglong2*)(Sj + 4 * (1 ^ key3));  // rows 4-7
            ulonglong2 p2 = *(const ulonglong2*)(Sj + 4 * (2 ^ key3));  // rows 8-11
            ulonglong2 p3 = *(const ulonglong2*)(Sj + 4 * (3 ^ key3));  // rows 12-15
            float v0 = buf[j * DK + d0];
            float v1 = buf[j * DK + d0 + 32];
            u64 vv0 = pk(v0, v0), vv1 = pk(v1, v1);
            fma2(acc2[0],  p0.x, vv0);  fma2(acc2[1],  p0.x, vv1);
            fma2(acc2[2],  p0.y, vv0);  fma2(acc2[3],  p0.y, vv1);
            fma2(acc2[4],  p1.x, vv0);  fma2(acc2[5],  p1.x, vv1);
            fma2(acc2[6],  p1.y, vv0);  fma2(acc2[7],  p1.y, vv1);
            fma2(acc2[8],  p2.x, vv0);  fma2(acc2[9],  p2.x, vv1);
            fma2(acc2[10], p2.y, vv0);  fma2(acc2[11], p2.y, vv1);
            fma2(acc2[12], p3.x, vv0);  fma2(acc2[13], p3.x, vv1);
            fma2(acc2[14], p3.y, vv0);  fma2(acc2[15], p3.y, vv1);
        }
    }

    // unpack: accf[k], k = rp*4 + dh*2 + half  (half: 0 = row 2rp, 1 = row 2rp+1)
    float accf[32];
#pragma unroll
    for (int rp = 0; rp < 8; rp++)
#pragma unroll
        for (int dh = 0; dh < 2; dh++) {
            float2 t = upk(acc2[rp * 2 + dh]);
            accf[rp * 4 + dh * 2 + 0] = t.x;
            accf[rp * 4 + dh * 2 + 1] = t.y;
        }

    // two-stage reduction across 16 jg groups (buf layout: k*256 + jg*32 + d0)
    __syncthreads();
    if (jg >= 8) {
        int base = (jg - 8) * 32 + d0;
#pragma unroll
        for (int k = 0; k < 32; k++) buf[k * 256 + base] = accf[k];
    }
    __syncthreads();
    if (jg < 8) {
        int base = jg * 32 + d0;
#pragma unroll
        for (int k = 0; k < 32; k++) accf[k] += buf[k * 256 + base];
    }
    __syncthreads();
    if (jg < 8) {
        int base = jg * 32 + d0;
#pragma unroll
        for (int k = 0; k < 32; k++) buf[k * 256 + base] = accf[k];
    }
    __syncthreads();
#pragma unroll
    for (int s = 0; s < 2; s++) {
        int oidx = tid + 512 * s;              // 1024 outputs = 16 r x 64 d
        int r = oidx >> 6, d = oidx & 63;
        int rp = r >> 1, half = r & 1, dh = d >> 5, dd0 = d & 31;
        int k = rp * 4 + dh * 2 + half;
        const float* p = buf + k * 256 + dd0;
        float sum = 0.f;
#pragma unroll
        for (int jg2 = 0; jg2 < 8; jg2++) sum += p[jg2 * 32];
        out[(size_t)(head * L + row0 + r) * DK + d] = sum * Cs[r];
    }
}

// ---------------------------------------------------------------------------
extern "C" void kernel_launch(void* const* d_in, const int* in_sizes, int n_in,
                              void* d_out, int out_size) {
    const float* q  = (const float*)d_in[0];
    const float* v  = (const float*)d_in[1];
    const float* Wa = (const float*)d_in[2];
    const float* ba = (const float*)d_in[3];
    const float* Wb = (const float*)d_in[4];
    const float* bb = (const float*)d_in[5];

    float* out  = (float*)d_out;                 // [H, L, DK]
    float* attn = out + (size_t)H * L * DK;      // [H, L, L]

    const int smem = (L * SPAD + ROWS * RB + 8192) * 4;   // 198656 B
    cudaFuncSetAttribute(attn_kernel, cudaFuncAttributeMaxDynamicSharedMemorySize, smem);

    proj_kernel<<<H * L / 64, 256>>>(q, Wa, ba, Wb, bb);
    attn_kernel<<<H * (L / ROWS), 512, smem>>>(v, out, attn);
}

// round 9
// speedup vs baseline: 3.2292x; 1.4007x over previous
#include <cuda_runtime.h>
#include <math.h>

#define H    16
#define L    2048
#define DK   64
#define RB   32
#define ROWS 16
#define SPAD 20          // padded row of S[j][.] in floats (16 data + 4 pad)

// Scratch (device globals: no allocs allowed)
__device__ float g_C[H * L * RB];
__device__ float g_B[H * L * RB];

// ---- f32x2 packed helpers --------------------------------------------------
typedef unsigned long long u64;

__device__ __forceinline__ u64 pk(float lo, float hi) {
    u64 r; asm("mov.b64 %0, {%1, %2};" : "=l"(r) : "f"(lo), "f"(hi)); return r;
}
__device__ __forceinline__ void fma2(u64 &acc, u64 a, u64 b) {
    asm("fma.rn.f32x2 %0, %1, %2, %0;" : "+l"(acc) : "l"(a), "l"(b));
}
__device__ __forceinline__ float2 upk(u64 v) {
    float2 r; asm("mov.b64 {%0, %1}, %2;" : "=f"(r.x), "=f"(r.y) : "l"(v)); return r;
}

// ---------------------------------------------------------------------------
// Kernel 1: projections (U built in-CTA; Wa/Wb are tiny and L1/L2-hot).
// CTA = 64 q-rows, 256 threads, 4x4 register tile per thread.
// C[m] = 32*(q.(Wa[2m]+Wa[2m+1]) + ba[2m]+ba[2m+1]);  B[m] = q.Wb[m] + bb[m]
// ---------------------------------------------------------------------------
__global__ __launch_bounds__(256)
void proj_kernel(const float* __restrict__ q,
                 const float* __restrict__ Wa, const float* __restrict__ ba,
                 const float* __restrict__ Wb, const float* __restrict__ bb) {
    __shared__ float Ut[DK * DK];   // [k][o]
    __shared__ float us[DK];
    __shared__ float qs[64 * DK];   // [r][k]
    int tid = threadIdx.x;
    int row0 = blockIdx.x * 64;

    for (int i = tid; i < DK * DK; i += 256) {
        int o = i >> 6, k = i & 63;
        float u;
        if (o < 32) u = 32.f * (Wa[(2 * o) * DK + k] + Wa[(2 * o + 1) * DK + k]);
        else        u = Wb[(o - 32) * DK + k];
        Ut[k * DK + o] = u;
    }
    if (tid < DK)
        us[tid] = (tid < 32) ? 32.f * (ba[2 * tid] + ba[2 * tid + 1]) : bb[tid - 32];
    {
        float4* q4 = (float4*)qs;  const float4* g4 = (const float4*)(q + (size_t)row0 * DK);
        for (int i = tid; i < 64 * DK / 4; i += 256) q4[i] = g4[i];
    }
    __syncthreads();

    int tr = tid >> 4, tc = tid & 15;
    float acc[4][4] = {};
#pragma unroll 8
    for (int k = 0; k < DK; k++) {
        float4 u = *(const float4*)(Ut + k * DK + 4 * tc);
        float qv[4];
#pragma unroll
        for (int ri = 0; ri < 4; ri++) qv[ri] = qs[(4 * tr + ri) * DK + k];
#pragma unroll
        for (int ri = 0; ri < 4; ri++) {
            acc[ri][0] += qv[ri] * u.x;  acc[ri][1] += qv[ri] * u.y;
            acc[ri][2] += qv[ri] * u.z;  acc[ri][3] += qv[ri] * u.w;
        }
    }
    float4 ub = *(const float4*)(us + 4 * tc);
#pragma unroll
    for (int ri = 0; ri < 4; ri++) {
        int row = row0 + 4 * tr + ri;
        float4 o = make_float4(acc[ri][0] + ub.x, acc[ri][1] + ub.y,
                               acc[ri][2] + ub.z, acc[ri][3] + ub.w);
        if (tc < 8) *(float4*)(g_C + (size_t)row * RB + 4 * tc)        = o;
        else        *(float4*)(g_B + (size_t)row * RB + (4 * tc - 32)) = o;
    }
}

// ---------------------------------------------------------------------------
// Kernel 2: fused attention. One CTA per (head, 16-row tile), 512 threads.
// S layout: S[j][16] in 4 float4-groups; group g stored at slot g^((j>>3)&1).
//  Phase 1: S = C @ B^T, thread = 2 j x 4 rows; C via full-warp broadcast LDS.
//  Phase 2: 3-pass softmax; inv kept in Cs[r]; attn STG coalesced.
//  Phase 3: E @ v; warp = 2 j, thread = 16 rows x 4 d; v direct LDG.128
//           (no staging, no barriers); epilogue reduction reuses S region.
// ---------------------------------------------------------------------------
__global__ __launch_bounds__(512, 1)
void attn_kernel(const float* __restrict__ v,
                 float* __restrict__ out,    // [H, L, DK]
                 float* __restrict__ attn) { // [H, L, L]
    extern __shared__ float sm[];
    float* S   = sm;                  // L * SPAD  = 40960 floats
    float* Cs  = S + L * SPAD;        // ROWS * RB = 512 (later: inv[16])
    float* buf = Cs + ROWS * RB;      // 8192 floats (B chunk staging)

    int tid  = threadIdx.x;
    int lane = tid & 31, w = tid >> 5;
    int head = blockIdx.x >> 7;
    int rt   = blockIdx.x & 127;
    int row0 = rt * ROWS;

    // C tile for these 16 rows
    {
        const float4* c4 = (const float4*)(g_C + (size_t)(head * L + row0) * RB);
        float4* d4 = (float4*)Cs;
        for (int i = tid; i < ROWS * RB / 4; i += 512) d4[i] = c4[i];
    }

    // ---- Phase 1: S[j][r] = sum_m C[r][m] * B[j][m] --------------------------
    const float* gB = g_B + (size_t)head * L * RB;
    int jq = tid & 127, rq = tid >> 7;        // 2 j per thread, 4-row quad rq
    for (int c = 0; c < 8; c++) {
        __syncthreads();                       // buf reuse guard (covers Cs fill)
        int j0 = c * 256;
        // stage swizzled B chunk: 256 j x 32 floats
#pragma unroll
        for (int t = 0; t < 4; t++) {
            int idx4 = tid + 512 * t;          // float4 index, 0..2047
            int j = idx4 >> 3, i = idx4 & 7;
            float4 bv = *(const float4*)(gB + (size_t)(j0 + j) * RB + 4 * i);
            *(float4*)(buf + j * RB + 4 * (i ^ (j & 7))) = bv;
        }
        __syncthreads();
        int jA = jq, jB = jq + 128;
        u64 acc[2][4];
#pragma unroll
        for (int a = 0; a < 2; a++)
#pragma unroll
            for (int b = 0; b < 4; b++) acc[a][b] = 0ull;
#pragma unroll
        for (int i = 0; i < 8; i++) {
            // full-warp broadcast (rq constant within warp)
            ulonglong2 c0 = *(const ulonglong2*)(Cs + (4 * rq + 0) * RB + 4 * i);
            ulonglong2 c1 = *(const ulonglong2*)(Cs + (4 * rq + 1) * RB + 4 * i);
            ulonglong2 c2 = *(const ulonglong2*)(Cs + (4 * rq + 2) * RB + 4 * i);
            ulonglong2 c3 = *(const ulonglong2*)(Cs + (4 * rq + 3) * RB + 4 * i);
            ulonglong2 bA = *(const ulonglong2*)(buf + jA * RB + 4 * (i ^ (jA & 7)));
            ulonglong2 bB = *(const ulonglong2*)(buf + jB * RB + 4 * (i ^ (jB & 7)));
            fma2(acc[0][0], c0.x, bA.x);  fma2(acc[0][0], c0.y, bA.y);
            fma2(acc[0][1], c1.x, bA.x);  fma2(acc[0][1], c1.y, bA.y);
            fma2(acc[0][2], c2.x, bA.x);  fma2(acc[0][2], c2.y, bA.y);
            fma2(acc[0][3], c3.x, bA.x);  fma2(acc[0][3], c3.y, bA.y);
            fma2(acc[1][0], c0.x, bB.x);  fma2(acc[1][0], c0.y, bB.y);
            fma2(acc[1][1], c1.x, bB.x);  fma2(acc[1][1], c1.y, bB.y);
            fma2(acc[1][2], c2.x, bB.x);  fma2(acc[1][2], c2.y, bB.y);
            fma2(acc[1][3], c3.x, bB.x);  fma2(acc[1][3], c3.y, bB.y);
        }
        {
            float2 t0 = upk(acc[0][0]), t1 = upk(acc[0][1]),
                   t2 = upk(acc[0][2]), t3 = upk(acc[0][3]);
            int key = (jA >> 3) & 1;
            *(float4*)(S + (size_t)(j0 + jA) * SPAD + 4 * (rq ^ key)) =
                make_float4(t0.x + t0.y, t1.x + t1.y, t2.x + t2.y, t3.x + t3.y);
        }
        {
            float2 t0 = upk(acc[1][0]), t1 = upk(acc[1][1]),
                   t2 = upk(acc[1][2]), t3 = upk(acc[1][3]);
            int key = (jB >> 3) & 1;
            *(float4*)(S + (size_t)(j0 + jB) * SPAD + 4 * (rq ^ key)) =
                make_float4(t0.x + t0.y, t1.x + t1.y, t2.x + t2.y, t3.x + t3.y);
        }
    }
    __syncthreads();

    // ---- Phase 2: softmax, warp w owns row w (3 passes) ---------------------
    {
        int r = w, g = r >> 2, e = r & 3;
        int off = 4 * (g ^ ((lane >> 3) & 1)) + e;   // per-lane constant slot
        float mx = -1e30f;
#pragma unroll
        for (int k = 0; k < 64; k++) mx = fmaxf(mx, S[(lane + 32 * k) * SPAD + off]);
#pragma unroll
        for (int o = 16; o > 0; o >>= 1) mx = fmaxf(mx, __shfl_xor_sync(0xffffffffu, mx, o));
        float sum = 0.f;
#pragma unroll
        for (int k = 0; k < 64; k++) {
            int idx = (lane + 32 * k) * SPAD + off;
            float ee = __expf(S[idx] - mx);
            S[idx] = ee;                  // keep unnormalized E
            sum += ee;
        }
#pragma unroll
        for (int o = 16; o > 0; o >>= 1) sum += __shfl_xor_sync(0xffffffffu, sum, o);
        float inv = 1.f / sum;
        if (lane == 0) Cs[r] = inv;       // Cs no longer needed as C
        float* ar = attn + (size_t)(head * L + row0 + r) * L;
#pragma unroll
        for (int k = 0; k < 64; k++) {
            int j = lane + 32 * k;
            ar[j] = S[j * SPAD + off] * inv;   // dense_attn (coalesced STG)
        }
    }
    __syncthreads();

    // ---- Phase 3: out = E @ v (v direct from global, no barriers) -----------
    int sub = (tid >> 4) & 1;            // which of the warp's 2 j
    int dq  = tid & 15;                  // d quad: d = 4dq..4dq+3
    const float* gv = v + (size_t)head * L * DK;
    u64 a3[8][4];
#pragma unroll
    for (int rp = 0; rp < 8; rp++)
#pragma unroll
        for (int di = 0; di < 4; di++) a3[rp][di] = 0ull;

#pragma unroll 8
    for (int t = 0; t < 64; t++) {
        int j = w * 128 + 2 * t + sub;
        float4 v4 = *(const float4*)(gv + (size_t)j * DK + 4 * dq);
        const float* Sj = S + (size_t)j * SPAD;
        int key = (j >> 3) & 1;
        ulonglong2 p0 = *(const ulonglong2*)(Sj + 4 * (0 ^ key));  // rows 0-3
        ulonglong2 p1 = *(const ulonglong2*)(Sj + 4 * (1 ^ key));  // rows 4-7
        ulonglong2 p2 = *(const ulonglong2*)(Sj + 4 * (2 ^ key));  // rows 8-11
        ulonglong2 p3 = *(const ulonglong2*)(Sj + 4 * (3 ^ key));  // rows 12-15
        u64 vv0 = pk(v4.x, v4.x), vv1 = pk(v4.y, v4.y);
        u64 vv2 = pk(v4.z, v4.z), vv3 = pk(v4.w, v4.w);
        fma2(a3[0][0], p0.x, vv0); fma2(a3[0][1], p0.x, vv1);
        fma2(a3[0][2], p0.x, vv2); fma2(a3[0][3], p0.x, vv3);
        fma2(a3[1][0], p0.y, vv0); fma2(a3[1][1], p0.y, vv1);
        fma2(a3[1][2], p0.y, vv2); fma2(a3[1][3], p0.y, vv3);
        fma2(a3[2][0], p1.x, vv0); fma2(a3[2][1], p1.x, vv1);
        fma2(a3[2][2], p1.x, vv2); fma2(a3[2][3], p1.x, vv3);
        fma2(a3[3][0], p1.y, vv0); fma2(a3[3][1], p1.y, vv1);
        fma2(a3[3][2], p1.y, vv2); fma2(a3[3][3], p1.y, vv3);
        fma2(a3[4][0], p2.x, vv0); fma2(a3[4][1], p2.x, vv1);
        fma2(a3[4][2], p2.x, vv2); fma2(a3[4][3], p2.x, vv3);
        fma2(a3[5][0], p2.y, vv0); fma2(a3[5][1], p2.y, vv1);
        fma2(a3[5][2], p2.y, vv2); fma2(a3[5][3], p2.y, vv3);
        fma2(a3[6][0], p3.x, vv0); fma2(a3[6][1], p3.x, vv1);
        fma2(a3[6][2], p3.x, vv2); fma2(a3[6][3], p3.x, vv3);
        fma2(a3[7][0], p3.y, vv0); fma2(a3[7][1], p3.y, vv1);
        fma2(a3[7][2], p3.y, vv2); fma2(a3[7][3], p3.y, vv3);
    }

    // ---- Epilogue: 32-way partial reduction; reuse dead S region ------------
    __syncthreads();                      // all threads done reading S
    {
        float* red = S;                   // [part][r][d] = part*1024 + r*64 + d
        int part = w * 2 + sub;
#pragma unroll
        for (int rp = 0; rp < 8; rp++) {
            float2 e0 = upk(a3[rp][0]), e1 = upk(a3[rp][1]);
            float2 e2 = upk(a3[rp][2]), e3 = upk(a3[rp][3]);
            *(float4*)(red + part * 1024 + (2 * rp)     * 64 + 4 * dq) =
                make_float4(e0.x, e1.x, e2.x, e3.x);
            *(float4*)(red + part * 1024 + (2 * rp + 1) * 64 + 4 * dq) =
                make_float4(e0.y, e1.y, e2.y, e3.y);
        }
        __syncthreads();
        int oq = tid >> 1, ph = tid & 1;          // 256 float4 outputs, 2 thr each
        int r = oq >> 4, dq2 = oq & 15;
        float4 s4 = make_float4(0.f, 0.f, 0.f, 0.f);
#pragma unroll
        for (int p = 0; p < 16; p++) {
            float4 t4 = *(const float4*)(red + (ph * 16 + p) * 1024 + r * 64 + 4 * dq2);
            s4.x += t4.x; s4.y += t4.y; s4.z += t4.z; s4.w += t4.w;
        }
        s4.x += __shfl_xor_sync(0xffffffffu, s4.x, 1);
        s4.y += __shfl_xor_sync(0xffffffffu, s4.y, 1);
        s4.z += __shfl_xor_sync(0xffffffffu, s4.z, 1);
        s4.w += __shfl_xor_sync(0xffffffffu, s4.w, 1);
        if (ph == 0) {
            float iv = Cs[r];
            *(float4*)(out + (size_t)(head * L + row0 + r) * DK + 4 * dq2) =
                make_float4(s4.x * iv, s4.y * iv, s4.z * iv, s4.w * iv);
        }
    }
}

// ---------------------------------------------------------------------------
extern "C" void kernel_launch(void* const* d_in, const int* in_sizes, int n_in,
                              void* d_out, int out_size) {
    const float* q  = (const float*)d_in[0];
    const float* v  = (const float*)d_in[1];
    const float* Wa = (const float*)d_in[2];
    const float* ba = (const float*)d_in[3];
    const float* Wb = (const float*)d_in[4];
    const float* bb = (const float*)d_in[5];

    float* out  = (float*)d_out;                 // [H, L, DK]
    float* attn = out + (size_t)H * L * DK;      // [H, L, L]

    const int smem = (L * SPAD + ROWS * RB + 8192) * 4;   // 198656 B
    cudaFuncSetAttribute(attn_kernel, cudaFuncAttributeMaxDynamicSharedMemorySize, smem);

    proj_kernel<<<H * L / 64, 256>>>(q, Wa, ba, Wb, bb);
    attn_kernel<<<H * (L / ROWS), 512, smem>>>(v, out, attn);
}

// round 10
// speedup vs baseline: 3.3745x; 1.0450x over previous
#include <cuda_runtime.h>
#include <math.h>

#define H    16
#define L    2048
#define DK   64
#define RB   32
#define ROWS 16
#define SPAD 20          // padded row of S[j][.] in floats (16 data + 4 pad)

// Scratch (device globals: no allocs allowed)
__device__ float g_C[H * L * RB];
__device__ float g_B[H * L * RB];

// ---- f32x2 packed helpers --------------------------------------------------
typedef unsigned long long u64;

__device__ __forceinline__ u64 pk(float lo, float hi) {
    u64 r; asm("mov.b64 %0, {%1, %2};" : "=l"(r) : "f"(lo), "f"(hi)); return r;
}
__device__ __forceinline__ void fma2(u64 &acc, u64 a, u64 b) {
    asm("fma.rn.f32x2 %0, %1, %2, %0;" : "+l"(acc) : "l"(a), "l"(b));
}
__device__ __forceinline__ float2 upk(u64 v) {
    float2 r; asm("mov.b64 {%0, %1}, %2;" : "=f"(r.x), "=f"(r.y) : "l"(v)); return r;
}
__device__ __forceinline__ void cp16(float* dst_smem, const float* src) {
    unsigned s = (unsigned)__cvta_generic_to_shared(dst_smem);
    asm volatile("cp.async.cg.shared.global [%0], [%1], 16;" :: "r"(s), "l"(src));
}
__device__ __forceinline__ void cp_commit() {
    asm volatile("cp.async.commit_group;");
}
__device__ __forceinline__ void cp_wait0() {
    asm volatile("cp.async.wait_group 0;");
}

// ---------------------------------------------------------------------------
// Kernel 1: projections (U built in-CTA; Wa/Wb are tiny and L1/L2-hot).
// CTA = 64 q-rows, 256 threads, 4x4 register tile per thread.
// C[m] = 32*(q.(Wa[2m]+Wa[2m+1]) + ba[2m]+ba[2m+1]);  B[m] = q.Wb[m] + bb[m]
// ---------------------------------------------------------------------------
__global__ __launch_bounds__(256)
void proj_kernel(const float* __restrict__ q,
                 const float* __restrict__ Wa, const float* __restrict__ ba,
                 const float* __restrict__ Wb, const float* __restrict__ bb) {
    __shared__ float Ut[DK * DK];   // [k][o]
    __shared__ float us[DK];
    __shared__ float qs[64 * DK];   // [r][k]
    int tid = threadIdx.x;
    int row0 = blockIdx.x * 64;

    for (int i = tid; i < DK * DK; i += 256) {
        int o = i >> 6, k = i & 63;
        float u;
        if (o < 32) u = 32.f * (Wa[(2 * o) * DK + k] + Wa[(2 * o + 1) * DK + k]);
        else        u = Wb[(o - 32) * DK + k];
        Ut[k * DK + o] = u;
    }
    if (tid < DK)
        us[tid] = (tid < 32) ? 32.f * (ba[2 * tid] + ba[2 * tid + 1]) : bb[tid - 32];
    {
        float4* q4 = (float4*)qs;  const float4* g4 = (const float4*)(q + (size_t)row0 * DK);
        for (int i = tid; i < 64 * DK / 4; i += 256) q4[i] = g4[i];
    }
    __syncthreads();

    int tr = tid >> 4, tc = tid & 15;
    float acc[4][4] = {};
#pragma unroll 8
    for (int k = 0; k < DK; k++) {
        float4 u = *(const float4*)(Ut + k * DK + 4 * tc);
        float qv[4];
#pragma unroll
        for (int ri = 0; ri < 4; ri++) qv[ri] = qs[(4 * tr + ri) * DK + k];
#pragma unroll
        for (int ri = 0; ri < 4; ri++) {
            acc[ri][0] += qv[ri] * u.x;  acc[ri][1] += qv[ri] * u.y;
            acc[ri][2] += qv[ri] * u.z;  acc[ri][3] += qv[ri] * u.w;
        }
    }
    float4 ub = *(const float4*)(us + 4 * tc);
#pragma unroll
    for (int ri = 0; ri < 4; ri++) {
        int row = row0 + 4 * tr + ri;
        float4 o = make_float4(acc[ri][0] + ub.x, acc[ri][1] + ub.y,
                               acc[ri][2] + ub.z, acc[ri][3] + ub.w);
        if (tc < 8) *(float4*)(g_C + (size_t)row * RB + 4 * tc)        = o;
        else        *(float4*)(g_B + (size_t)row * RB + (4 * tc - 32)) = o;
    }
}

// ---------------------------------------------------------------------------
// Kernel 2: fused attention. One CTA per (head, 16-row tile), 512 threads.
// S layout: S[j][16] in 4 float4-groups; group g stored at slot g^((j>>3)&1).
//  Phase 1: S = C @ B^T; B staged via double-buffered cp.async (1 barrier/chunk,
//           copy of chunk c+1 overlaps compute of chunk c).
//  Phase 2: 3-pass softmax; inv kept in Cs[r]; attn STG coalesced.
//  Phase 3: E @ v; v direct LDG.128 with 1-iteration software prefetch;
//           epilogue reduction reuses dead S region.
// ---------------------------------------------------------------------------
__global__ __launch_bounds__(512, 1)
void attn_kernel(const float* __restrict__ v,
                 float* __restrict__ out,    // [H, L, DK]
                 float* __restrict__ attn) { // [H, L, L]
    extern __shared__ float sm[];
    float* S   = sm;                  // L * SPAD  = 40960 floats
    float* Cs  = S + L * SPAD;        // ROWS * RB = 512 (later: inv[16])
    float* buf = Cs + ROWS * RB;      // 2 x 8192 floats (double-buffered B chunks)

    int tid  = threadIdx.x;
    int lane = tid & 31, w = tid >> 5;
    int head = blockIdx.x >> 7;
    int rt   = blockIdx.x & 127;
    int row0 = rt * ROWS;

    const float* gB = g_B + (size_t)head * L * RB;

    // Issue chunk 0 copy first (overlaps with Cs fill below)
    {
        float* b0 = buf;
#pragma unroll
        for (int t = 0; t < 4; t++) {
            int idx4 = tid + 512 * t;              // float4 index, 0..2047
            int j = idx4 >> 3, i = idx4 & 7;
            cp16(b0 + j * RB + 4 * (i ^ (j & 7)), gB + (size_t)j * RB + 4 * i);
        }
        cp_commit();
    }

    // C tile for these 16 rows
    {
        const float4* c4 = (const float4*)(g_C + (size_t)(head * L + row0) * RB);
        float4* d4 = (float4*)Cs;
        for (int i = tid; i < ROWS * RB / 4; i += 512) d4[i] = c4[i];
    }

    // ---- Phase 1: S[j][r] = sum_m C[r][m] * B[j][m] --------------------------
    int jq = tid & 127, rq = tid >> 7;        // 2 j per thread, 4-row quad rq
    for (int c = 0; c < 8; c++) {
        cp_wait0();
        __syncthreads();                       // chunk c visible; prev buffer free
        if (c < 7) {                           // prefetch chunk c+1 into other buf
            float* bn = buf + ((c + 1) & 1) * 8192;
            int j0n = (c + 1) * 256;
#pragma unroll
            for (int t = 0; t < 4; t++) {
                int idx4 = tid + 512 * t;
                int j = idx4 >> 3, i = idx4 & 7;
                cp16(bn + j * RB + 4 * (i ^ (j & 7)),
                     gB + (size_t)(j0n + j) * RB + 4 * i);
            }
            cp_commit();
        }
        const float* bc = buf + (c & 1) * 8192;
        int j0 = c * 256;
        int jA = jq, jB = jq + 128;
        u64 acc[2][4];
#pragma unroll
        for (int a = 0; a < 2; a++)
#pragma unroll
            for (int b = 0; b < 4; b++) acc[a][b] = 0ull;
#pragma unroll
        for (int i = 0; i < 8; i++) {
            // full-warp broadcast (rq constant within warp)
            ulonglong2 c0 = *(const ulonglong2*)(Cs + (4 * rq + 0) * RB + 4 * i);
            ulonglong2 c1 = *(const ulonglong2*)(Cs + (4 * rq + 1) * RB + 4 * i);
            ulonglong2 c2 = *(const ulonglong2*)(Cs + (4 * rq + 2) * RB + 4 * i);
            ulonglong2 c3 = *(const ulonglong2*)(Cs + (4 * rq + 3) * RB + 4 * i);
            ulonglong2 bA = *(const ulonglong2*)(bc + jA * RB + 4 * (i ^ (jA & 7)));
            ulonglong2 bB = *(const ulonglong2*)(bc + jB * RB + 4 * (i ^ (jB & 7)));
            fma2(acc[0][0], c0.x, bA.x);  fma2(acc[0][0], c0.y, bA.y);
            fma2(acc[0][1], c1.x, bA.x);  fma2(acc[0][1], c1.y, bA.y);
            fma2(acc[0][2], c2.x, bA.x);  fma2(acc[0][2], c2.y, bA.y);
            fma2(acc[0][3], c3.x, bA.x);  fma2(acc[0][3], c3.y, bA.y);
            fma2(acc[1][0], c0.x, bB.x);  fma2(acc[1][0], c0.y, bB.y);
            fma2(acc[1][1], c1.x, bB.x);  fma2(acc[1][1], c1.y, bB.y);
            fma2(acc[1][2], c2.x, bB.x);  fma2(acc[1][2], c2.y, bB.y);
            fma2(acc[1][3], c3.x, bB.x);  fma2(acc[1][3], c3.y, bB.y);
        }
        {
            float2 t0 = upk(acc[0][0]), t1 = upk(acc[0][1]),
                   t2 = upk(acc[0][2]), t3 = upk(acc[0][3]);
            int key = (jA >> 3) & 1;
            *(float4*)(S + (size_t)(j0 + jA) * SPAD + 4 * (rq ^ key)) =
                make_float4(t0.x + t0.y, t1.x + t1.y, t2.x + t2.y, t3.x + t3.y);
        }
        {
            float2 t0 = upk(acc[1][0]), t1 = upk(acc[1][1]),
                   t2 = upk(acc[1][2]), t3 = upk(acc[1][3]);
            int key = (jB >> 3) & 1;
            *(float4*)(S + (size_t)(j0 + jB) * SPAD + 4 * (rq ^ key)) =
                make_float4(t0.x + t0.y, t1.x + t1.y, t2.x + t2.y, t3.x + t3.y);
        }
    }
    __syncthreads();

    // ---- Phase 2: softmax, warp w owns row w (3 passes) ---------------------
    {
        int r = w, g = r >> 2, e = r & 3;
        int off = 4 * (g ^ ((lane >> 3) & 1)) + e;   // per-lane constant slot
        float mx = -1e30f;
#pragma unroll
        for (int k = 0; k < 64; k++) mx = fmaxf(mx, S[(lane + 32 * k) * SPAD + off]);
#pragma unroll
        for (int o = 16; o > 0; o >>= 1) mx = fmaxf(mx, __shfl_xor_sync(0xffffffffu, mx, o));
        float sum = 0.f;
#pragma unroll
        for (int k = 0; k < 64; k++) {
            int idx = (lane + 32 * k) * SPAD + off;
            float ee = __expf(S[idx] - mx);
            S[idx] = ee;                  // keep unnormalized E
            sum += ee;
        }
#pragma unroll
        for (int o = 16; o > 0; o >>= 1) sum += __shfl_xor_sync(0xffffffffu, sum, o);
        float inv = 1.f / sum;
        if (lane == 0) Cs[r] = inv;       // Cs no longer needed as C
        float* ar = attn + (size_t)(head * L + row0 + r) * L;
#pragma unroll
        for (int k = 0; k < 64; k++) {
            int j = lane + 32 * k;
            ar[j] = S[j * SPAD + off] * inv;   // dense_attn (coalesced STG)
        }
    }
    __syncthreads();

    // ---- Phase 3: out = E @ v (v direct LDG, 1-iter prefetch, no barriers) --
    int sub = (tid >> 4) & 1;            // which of the warp's 2 j
    int dq  = tid & 15;                  // d quad: d = 4dq..4dq+3
    const float* gv = v + (size_t)head * L * DK;
    u64 a3[8][4];
#pragma unroll
    for (int rp = 0; rp < 8; rp++)
#pragma unroll
        for (int di = 0; di < 4; di++) a3[rp][di] = 0ull;

    int jbase = w * 128 + sub;
    float4 v4 = *(const float4*)(gv + (size_t)jbase * DK + 4 * dq);
#pragma unroll 4
    for (int t = 0; t < 64; t++) {
        int j = jbase + 2 * t;
        int jn = j + 2 <= jbase + 126 ? j + 2 : jbase + 126;   // clamp tail
        float4 v4n = *(const float4*)(gv + (size_t)jn * DK + 4 * dq);
        const float* Sj = S + (size_t)j * SPAD;
        int key = (j >> 3) & 1;
        ulonglong2 p0 = *(const ulonglong2*)(Sj + 4 * (0 ^ key));  // rows 0-3
        ulonglong2 p1 = *(const ulonglong2*)(Sj + 4 * (1 ^ key));  // rows 4-7
        ulonglong2 p2 = *(const ulonglong2*)(Sj + 4 * (2 ^ key));  // rows 8-11
        ulonglong2 p3 = *(const ulonglong2*)(Sj + 4 * (3 ^ key));  // rows 12-15
        u64 vv0 = pk(v4.x, v4.x), vv1 = pk(v4.y, v4.y);
        u64 vv2 = pk(v4.z, v4.z), vv3 = pk(v4.w, v4.w);
        fma2(a3[0][0], p0.x, vv0); fma2(a3[0][1], p0.x, vv1);
        fma2(a3[0][2], p0.x, vv2); fma2(a3[0][3], p0.x, vv3);
        fma2(a3[1][0], p0.y, vv0); fma2(a3[1][1], p0.y, vv1);
        fma2(a3[1][2], p0.y, vv2); fma2(a3[1][3], p0.y, vv3);
        fma2(a3[2][0], p1.x, vv0); fma2(a3[2][1], p1.x, vv1);
        fma2(a3[2][2], p1.x, vv2); fma2(a3[2][3], p1.x, vv3);
        fma2(a3[3][0], p1.y, vv0); fma2(a3[3][1], p1.y, vv1);
        fma2(a3[3][2], p1.y, vv2); fma2(a3[3][3], p1.y, vv3);
        fma2(a3[4][0], p2.x, vv0); fma2(a3[4][1], p2.x, vv1);
        fma2(a3[4][2], p2.x, vv2); fma2(a3[4][3], p2.x, vv3);
        fma2(a3[5][0], p2.y, vv0); fma2(a3[5][1], p2.y, vv1);
        fma2(a3[5][2], p2.y, vv2); fma2(a3[5][3], p2.y, vv3);
        fma2(a3[6][0], p3.x, vv0); fma2(a3[6][1], p3.x, vv1);
        fma2(a3[6][2], p3.x, vv2); fma2(a3[6][3], p3.x, vv3);
        fma2(a3[7][0], p3.y, vv0); fma2(a3[7][1], p3.y, vv1);
        fma2(a3[7][2], p3.y, vv2); fma2(a3[7][3], p3.y, vv3);
        v4 = v4n;
    }

    // ---- Epilogue: 32-way partial reduction; reuse dead S region ------------
    __syncthreads();                      // all threads done reading S
    {
        float* red = S;                   // [part][r][d] = part*1024 + r*64 + d
        int part = w * 2 + sub;
#pragma unroll
        for (int rp = 0; rp < 8; rp++) {
            float2 e0 = upk(a3[rp][0]), e1 = upk(a3[rp][1]);
            float2 e2 = upk(a3[rp][2]), e3 = upk(a3[rp][3]);
            *(float4*)(red + part * 1024 + (2 * rp)     * 64 + 4 * dq) =
                make_float4(e0.x, e1.x, e2.x, e3.x);
            *(float4*)(red + part * 1024 + (2 * rp + 1) * 64 + 4 * dq) =
                make_float4(e0.y, e1.y, e2.y, e3.y);
        }
        __syncthreads();
        int oq = tid >> 1, ph = tid & 1;          // 256 float4 outputs, 2 thr each
        int r = oq >> 4, dq2 = oq & 15;
        float4 s4 = make_float4(0.f, 0.f, 0.f, 0.f);
#pragma unroll
        for (int p = 0; p < 16; p++) {
            float4 t4 = *(const float4*)(red + (ph * 16 + p) * 1024 + r * 64 + 4 * dq2);
            s4.x += t4.x; s4.y += t4.y; s4.z += t4.z; s4.w += t4.w;
        }
        s4.x += __shfl_xor_sync(0xffffffffu, s4.x, 1);
        s4.y += __shfl_xor_sync(0xffffffffu, s4.y, 1);
        s4.z += __shfl_xor_sync(0xffffffffu, s4.z, 1);
        s4.w += __shfl_xor_sync(0xffffffffu, s4.w, 1);
        if (ph == 0) {
            float iv = Cs[r];
            *(float4*)(out + (size_t)(head * L + row0 + r) * DK + 4 * dq2) =
                make_float4(s4.x * iv, s4.y * iv, s4.z * iv, s4.w * iv);
        }
    }
}

// ---------------------------------------------------------------------------
extern "C" void kernel_launch(void* const* d_in, const int* in_sizes, int n_in,
                              void* d_out, int out_size) {
    const float* q  = (const float*)d_in[0];
    const float* v  = (const float*)d_in[1];
    const float* Wa = (const float*)d_in[2];
    const float* ba = (const float*)d_in[3];
    const float* Wb = (const float*)d_in[4];
    const float* bb = (const float*)d_in[5];

    float* out  = (float*)d_out;                 // [H, L, DK]
    float* attn = out + (size_t)H * L * DK;      // [H, L, L]

    const int smem = (L * SPAD + ROWS * RB + 2 * 8192) * 4;   // 231424 B
    cudaFuncSetAttribute(attn_kernel, cudaFuncAttributeMaxDynamicSharedMemorySize, smem);

    proj_kernel<<<H * L / 64, 256>>>(q, Wa, ba, Wb, bb);
    attn_kernel<<<H * (L / ROWS), 512, smem>>>(v, out, attn);
}

// round 11
// speedup vs baseline: 3.5185x; 1.0427x over previous
#include <cuda_runtime.h>
#include <math.h>

#define H    16
#define L    2048
#define DK   64
#define RB   32
#define ROWS 16
#define SPAD 20          // padded row of S[j][.] in floats (16 data + 4 pad)

// Scratch (device globals: no allocs allowed)
__device__ float g_C[H * L * RB];
__device__ float g_B[H * L * RB];

// ---- f32x2 packed helpers --------------------------------------------------
typedef unsigned long long u64;

__device__ __forceinline__ u64 pk(float lo, float hi) {
    u64 r; asm("mov.b64 %0, {%1, %2};" : "=l"(r) : "f"(lo), "f"(hi)); return r;
}
__device__ __forceinline__ void fma2(u64 &acc, u64 a, u64 b) {
    asm("fma.rn.f32x2 %0, %1, %2, %0;" : "+l"(acc) : "l"(a), "l"(b));
}
__device__ __forceinline__ float2 upk(u64 v) {
    float2 r; asm("mov.b64 {%0, %1}, %2;" : "=f"(r.x), "=f"(r.y) : "l"(v)); return r;
}
__device__ __forceinline__ void cp16(float* dst_smem, const float* src) {
    unsigned s = (unsigned)__cvta_generic_to_shared(dst_smem);
    asm volatile("cp.async.cg.shared.global [%0], [%1], 16;" :: "r"(s), "l"(src));
}
__device__ __forceinline__ void cp_commit() {
    asm volatile("cp.async.commit_group;");
}
__device__ __forceinline__ void cp_wait0() {
    asm volatile("cp.async.wait_group 0;");
}

// ---------------------------------------------------------------------------
// Kernel 1: projections (U built in-CTA; Wa/Wb are tiny and L1/L2-hot).
// ---------------------------------------------------------------------------
__global__ __launch_bounds__(256)
void proj_kernel(const float* __restrict__ q,
                 const float* __restrict__ Wa, const float* __restrict__ ba,
                 const float* __restrict__ Wb, const float* __restrict__ bb) {
    __shared__ float Ut[DK * DK];   // [k][o]
    __shared__ float us[DK];
    __shared__ float qs[64 * DK];   // [r][k]
    int tid = threadIdx.x;
    int row0 = blockIdx.x * 64;

    for (int i = tid; i < DK * DK; i += 256) {
        int o = i >> 6, k = i & 63;
        float u;
        if (o < 32) u = 32.f * (Wa[(2 * o) * DK + k] + Wa[(2 * o + 1) * DK + k]);
        else        u = Wb[(o - 32) * DK + k];
        Ut[k * DK + o] = u;
    }
    if (tid < DK)
        us[tid] = (tid < 32) ? 32.f * (ba[2 * tid] + ba[2 * tid + 1]) : bb[tid - 32];
    {
        float4* q4 = (float4*)qs;  const float4* g4 = (const float4*)(q + (size_t)row0 * DK);
        for (int i = tid; i < 64 * DK / 4; i += 256) q4[i] = g4[i];
    }
    __syncthreads();

    int tr = tid >> 4, tc = tid & 15;
    float acc[4][4] = {};
#pragma unroll 8
    for (int k = 0; k < DK; k++) {
        float4 u = *(const float4*)(Ut + k * DK + 4 * tc);
        float qv[4];
#pragma unroll
        for (int ri = 0; ri < 4; ri++) qv[ri] = qs[(4 * tr + ri) * DK + k];
#pragma unroll
        for (int ri = 0; ri < 4; ri++) {
            acc[ri][0] += qv[ri] * u.x;  acc[ri][1] += qv[ri] * u.y;
            acc[ri][2] += qv[ri] * u.z;  acc[ri][3] += qv[ri] * u.w;
        }
    }
    float4 ub = *(const float4*)(us + 4 * tc);
#pragma unroll
    for (int ri = 0; ri < 4; ri++) {
        int row = row0 + 4 * tr + ri;
        float4 o = make_float4(acc[ri][0] + ub.x, acc[ri][1] + ub.y,
                               acc[ri][2] + ub.z, acc[ri][3] + ub.w);
        if (tc < 8) *(float4*)(g_C + (size_t)row * RB + 4 * tc)        = o;
        else        *(float4*)(g_B + (size_t)row * RB + (4 * tc - 32)) = o;
    }
}

// ---------------------------------------------------------------------------
// Kernel 2: fused attention. One CTA per (head, 16-row tile), 512 threads.
// S layout: S[j][16] in 4 float4-groups; group g stored at slot g^((j>>3)&1).
//  Phase 1: S = C @ B^T; B via double-buffered cp.async (1 barrier/chunk).
//  Phase 2: 3-pass softmax, marching pointers; inv in Cs[r].
//  Phase 3: E @ v; v LDG.128 prefetch distance 2; key hoisted per 4-iter
//           group; marching pointers; epilogue reduction reuses dead S.
// ---------------------------------------------------------------------------
__global__ __launch_bounds__(512, 1)
void attn_kernel(const float* __restrict__ v,
                 float* __restrict__ out,    // [H, L, DK]
                 float* __restrict__ attn) { // [H, L, L]
    extern __shared__ float sm[];
    float* S   = sm;                  // L * SPAD  = 40960 floats
    float* Cs  = S + L * SPAD;        // ROWS * RB = 512 (later: inv[16])
    float* buf = Cs + ROWS * RB;      // 2 x 8192 floats (double-buffered B chunks)

    int tid  = threadIdx.x;
    int lane = tid & 31, w = tid >> 5;
    int head = blockIdx.x >> 7;
    int rt   = blockIdx.x & 127;
    int row0 = rt * ROWS;

    const float* gB = g_B + (size_t)head * L * RB;

    // Issue chunk 0 copy first (overlaps with Cs fill below)
    {
        float* b0 = buf;
#pragma unroll
        for (int t = 0; t < 4; t++) {
            int idx4 = tid + 512 * t;              // float4 index, 0..2047
            int j = idx4 >> 3, i = idx4 & 7;
            cp16(b0 + j * RB + 4 * (i ^ (j & 7)), gB + (size_t)j * RB + 4 * i);
        }
        cp_commit();
    }

    // C tile for these 16 rows
    {
        const float4* c4 = (const float4*)(g_C + (size_t)(head * L + row0) * RB);
        float4* d4 = (float4*)Cs;
        for (int i = tid; i < ROWS * RB / 4; i += 512) d4[i] = c4[i];
    }

    // ---- Phase 1: S[j][r] = sum_m C[r][m] * B[j][m] --------------------------
    int jq = tid & 127, rq = tid >> 7;        // 2 j per thread, 4-row quad rq
    for (int c = 0; c < 8; c++) {
        cp_wait0();
        __syncthreads();                       // chunk c visible; prev buffer free
        if (c < 7) {                           // prefetch chunk c+1 into other buf
            float* bn = buf + ((c + 1) & 1) * 8192;
            const float* gn = gB + (size_t)(c + 1) * 256 * RB;
#pragma unroll
            for (int t = 0; t < 4; t++) {
                int idx4 = tid + 512 * t;
                int j = idx4 >> 3, i = idx4 & 7;
                cp16(bn + j * RB + 4 * (i ^ (j & 7)), gn + (size_t)j * RB + 4 * i);
            }
            cp_commit();
        }
        const float* bc = buf + (c & 1) * 8192;
        int j0 = c * 256;
        int jA = jq, jB = jq + 128;
        u64 acc[2][4];
#pragma unroll
        for (int a = 0; a < 2; a++)
#pragma unroll
            for (int b = 0; b < 4; b++) acc[a][b] = 0ull;
#pragma unroll
        for (int i = 0; i < 8; i++) {
            // full-warp broadcast (rq constant within warp)
            ulonglong2 c0 = *(const ulonglong2*)(Cs + (4 * rq + 0) * RB + 4 * i);
            ulonglong2 c1 = *(const ulonglong2*)(Cs + (4 * rq + 1) * RB + 4 * i);
            ulonglong2 c2 = *(const ulonglong2*)(Cs + (4 * rq + 2) * RB + 4 * i);
            ulonglong2 c3 = *(const ulonglong2*)(Cs + (4 * rq + 3) * RB + 4 * i);
            ulonglong2 bA = *(const ulonglong2*)(bc + jA * RB + 4 * (i ^ (jA & 7)));
            ulonglong2 bB = *(const ulonglong2*)(bc + jB * RB + 4 * (i ^ (jB & 7)));
            fma2(acc[0][0], c0.x, bA.x);  fma2(acc[0][0], c0.y, bA.y);
            fma2(acc[0][1], c1.x, bA.x);  fma2(acc[0][1], c1.y, bA.y);
            fma2(acc[0][2], c2.x, bA.x);  fma2(acc[0][2], c2.y, bA.y);
            fma2(acc[0][3], c3.x, bA.x);  fma2(acc[0][3], c3.y, bA.y);
            fma2(acc[1][0], c0.x, bB.x);  fma2(acc[1][0], c0.y, bB.y);
            fma2(acc[1][1], c1.x, bB.x);  fma2(acc[1][1], c1.y, bB.y);
            fma2(acc[1][2], c2.x, bB.x);  fma2(acc[1][2], c2.y, bB.y);
            fma2(acc[1][3], c3.x, bB.x);  fma2(acc[1][3], c3.y, bB.y);
        }
        {
            float2 t0 = upk(acc[0][0]), t1 = upk(acc[0][1]),
                   t2 = upk(acc[0][2]), t3 = upk(acc[0][3]);
            int key = (jA >> 3) & 1;
            *(float4*)(S + (size_t)(j0 + jA) * SPAD + 4 * (rq ^ key)) =
                make_float4(t0.x + t0.y, t1.x + t1.y, t2.x + t2.y, t3.x + t3.y);
        }
        {
            float2 t0 = upk(acc[1][0]), t1 = upk(acc[1][1]),
                   t2 = upk(acc[1][2]), t3 = upk(acc[1][3]);
            int key = (jB >> 3) & 1;
            *(float4*)(S + (size_t)(j0 + jB) * SPAD + 4 * (rq ^ key)) =
                make_float4(t0.x + t0.y, t1.x + t1.y, t2.x + t2.y, t3.x + t3.y);
        }
    }
    __syncthreads();

    // ---- Phase 2: softmax, warp w owns row w (3 passes, marching ptrs) ------
    {
        int r = w, g = r >> 2, e = r & 3;
        int off = 4 * (g ^ ((lane >> 3) & 1)) + e;   // per-lane constant slot
        const float* p0 = S + lane * SPAD + off;
        float mx = -1e30f;
#pragma unroll
        for (int k = 0; k < 64; k++) { mx = fmaxf(mx, *p0); p0 += 32 * SPAD; }
#pragma unroll
        for (int o = 16; o > 0; o >>= 1) mx = fmaxf(mx, __shfl_xor_sync(0xffffffffu, mx, o));
        float* p1 = S + lane * SPAD + off;
        float sum = 0.f;
#pragma unroll
        for (int k = 0; k < 64; k++) {
            float ee = __expf(*p1 - mx);
            *p1 = ee;                     // keep unnormalized E
            sum += ee;
            p1 += 32 * SPAD;
        }
#pragma unroll
        for (int o = 16; o > 0; o >>= 1) sum += __shfl_xor_sync(0xffffffffu, sum, o);
        float inv = 1.f / sum;
        if (lane == 0) Cs[r] = inv;       // Cs no longer needed as C
        const float* p2 = S + lane * SPAD + off;
        float* ar = attn + (size_t)(head * L + row0 + r) * L + lane;
#pragma unroll
        for (int k = 0; k < 64; k++) {
            *ar = *p2 * inv;              // dense_attn (coalesced STG)
            p2 += 32 * SPAD;  ar += 32;
        }
    }
    __syncthreads();

    // ---- Phase 3: out = E @ v (LDG prefetch dist 2; key hoisted per group) --
    int sub = (tid >> 4) & 1;            // which of the warp's 2 j
    int dq  = tid & 15;                  // d quad: d = 4dq..4dq+3
    const float* gv = v + (size_t)head * L * DK;
    u64 a3[8][4];
#pragma unroll
    for (int rp = 0; rp < 8; rp++)
#pragma unroll
        for (int di = 0; di < 4; di++) a3[rp][di] = 0ull;

    int jbase = w * 128 + sub;
    const float* vp  = gv + (size_t)jbase * DK + 4 * dq;
    const float* vpn = vp + 4 * DK;                     // t+2 prefetch stream
    const float* Sjp = S + (size_t)jbase * SPAD;
    float4 v4  = *(const float4*)vp;
    float4 v4b = *(const float4*)(vp + 2 * DK);

    for (int g = 0; g < 16; g++) {
        int key = g & 1;                  // (j>>3)&1 constant over this group
        int o0 = 4 * key, o1 = 4 - o0, o2 = 8 + o0, o3 = 12 - o0;
#pragma unroll
        for (int t2 = 0; t2 < 4; t2++) {
            int t = 4 * g + t2;
            float4 v4c = v4b;
            if (t < 62) v4c = *(const float4*)vpn;
            vpn += 2 * DK;
            ulonglong2 p0 = *(const ulonglong2*)(Sjp + o0);  // rows 0-3
            ulonglong2 p1 = *(const ulonglong2*)(Sjp + o1);  // rows 4-7
            ulonglong2 p2 = *(const ulonglong2*)(Sjp + o2);  // rows 8-11
            ulonglong2 p3 = *(const ulonglong2*)(Sjp + o3);  // rows 12-15
            Sjp += 2 * SPAD;
            u64 vv0 = pk(v4.x, v4.x), vv1 = pk(v4.y, v4.y);
            u64 vv2 = pk(v4.z, v4.z), vv3 = pk(v4.w, v4.w);
            fma2(a3[0][0], p0.x, vv0); fma2(a3[0][1], p0.x, vv1);
            fma2(a3[0][2], p0.x, vv2); fma2(a3[0][3], p0.x, vv3);
            fma2(a3[1][0], p0.y, vv0); fma2(a3[1][1], p0.y, vv1);
            fma2(a3[1][2], p0.y, vv2); fma2(a3[1][3], p0.y, vv3);
            fma2(a3[2][0], p1.x, vv0); fma2(a3[2][1], p1.x, vv1);
            fma2(a3[2][2], p1.x, vv2); fma2(a3[2][3], p1.x, vv3);
            fma2(a3[3][0], p1.y, vv0); fma2(a3[3][1], p1.y, vv1);
            fma2(a3[3][2], p1.y, vv2); fma2(a3[3][3], p1.y, vv3);
            fma2(a3[4][0], p2.x, vv0); fma2(a3[4][1], p2.x, vv1);
            fma2(a3[4][2], p2.x, vv2); fma2(a3[4][3], p2.x, vv3);
            fma2(a3[5][0], p2.y, vv0); fma2(a3[5][1], p2.y, vv1);
            fma2(a3[5][2], p2.y, vv2); fma2(a3[5][3], p2.y, vv3);
            fma2(a3[6][0], p3.x, vv0); fma2(a3[6][1], p3.x, vv1);
            fma2(a3[6][2], p3.x, vv2); fma2(a3[6][3], p3.x, vv3);
            fma2(a3[7][0], p3.y, vv0); fma2(a3[7][1], p3.y, vv1);
            fma2(a3[7][2], p3.y, vv2); fma2(a3[7][3], p3.y, vv3);
            v4 = v4b;  v4b = v4c;
        }
    }

    // ---- Epilogue: 32-way partial reduction; reuse dead S region ------------
    __syncthreads();                      // all threads done reading S
    {
        float* red = S;                   // [part][r][d] = part*1024 + r*64 + d
        int part = w * 2 + sub;
#pragma unroll
        for (int rp = 0; rp < 8; rp++) {
            float2 e0 = upk(a3[rp][0]), e1 = upk(a3[rp][1]);
            float2 e2 = upk(a3[rp][2]), e3 = upk(a3[rp][3]);
            *(float4*)(red + part * 1024 + (2 * rp)     * 64 + 4 * dq) =
                make_float4(e0.x, e1.x, e2.x, e3.x);
            *(float4*)(red + part * 1024 + (2 * rp + 1) * 64 + 4 * dq) =
                make_float4(e0.y, e1.y, e2.y, e3.y);
        }
        __syncthreads();
        int oq = tid >> 1, ph = tid & 1;          // 256 float4 outputs, 2 thr each
        int r = oq >> 4, dq2 = oq & 15;
        float4 s4 = make_float4(0.f, 0.f, 0.f, 0.f);
        const float* rp2 = red + ph * 16384 + r * 64 + 4 * dq2;
#pragma unroll
        for (int p = 0; p < 16; p++) {
            float4 t4 = *(const float4*)rp2;
            s4.x += t4.x; s4.y += t4.y; s4.z += t4.z; s4.w += t4.w;
            rp2 += 1024;
        }
        s4.x += __shfl_xor_sync(0xffffffffu, s4.x, 1);
        s4.y += __shfl_xor_sync(0xffffffffu, s4.y, 1);
        s4.z += __shfl_xor_sync(0xffffffffu, s4.z, 1);
        s4.w += __shfl_xor_sync(0xffffffffu, s4.w, 1);
        if (ph == 0) {
            float iv = Cs[r];
            *(float4*)(out + (size_t)(head * L + row0 + r) * DK + 4 * dq2) =
                make_float4(s4.x * iv, s4.y * iv, s4.z * iv, s4.w * iv);
        }
    }
}

// ---------------------------------------------------------------------------
extern "C" void kernel_launch(void* const* d_in, const int* in_sizes, int n_in,
                              void* d_out, int out_size) {
    const float* q  = (const float*)d_in[0];
    const float* v  = (const float*)d_in[1];
    const float* Wa = (const float*)d_in[2];
    const float* ba = (const float*)d_in[3];
    const float* Wb = (const float*)d_in[4];
    const float* bb = (const float*)d_in[5];

    float* out  = (float*)d_out;                 // [H, L, DK]
    float* attn = out + (size_t)H * L * DK;      // [H, L, L]

    const int smem = (L * SPAD + ROWS * RB + 2 * 8192) * 4;   // 231424 B
    cudaFuncSetAttribute(attn_kernel, cudaFuncAttributeMaxDynamicSharedMemorySize, smem);

    proj_kernel<<<H * L / 64, 256>>>(q, Wa, ba, Wb, bb);
    attn_kernel<<<H * (L / ROWS), 512, smem>>>(v, out, attn);
}